// round 2
// baseline (speedup 1.0000x reference)
#include <cuda_runtime.h>

// Problem constants (fixed by setup_inputs)
#define B_   2
#define S_   2048
#define DM_  1024
#define H_   16
#define D_   64
#define NB_  5        // 2*MAX_REL+1
#define SCALE_ 0.125f // 1/sqrt(64)
#define LOG2E_ 1.4426950408889634f

// Static device scratch (allocation-free rule)
__device__ float g_q[B_*H_*S_*D_];
__device__ float g_k[B_*H_*S_*D_];
__device__ float g_v[B_*H_*S_*D_];
__device__ float g_att[B_*S_*DM_];

// ---------------------------------------------------------------------------
// Generic 64x64-tile SGEMM: out = X @ W + bias
// X: [4096, 1024] row-major, W: [1024, 1024] row-major.
// permute=1 -> write out[((b*H+h)*S+s)*D+d]  (BHSD layout for q/k/v)
// permute=0 -> write out[m*DM+n]             (plain row-major)
// ---------------------------------------------------------------------------
__global__ __launch_bounds__(256) void sgemm64(
    const float* __restrict__ X, const float* __restrict__ W,
    const float* __restrict__ bias, float* __restrict__ out, int permute)
{
    __shared__ float Xs[16][68];  // [k][row], padded
    __shared__ float Ws[16][64];  // [k][col]
    const int tid = threadIdx.x;
    const int tx = tid & 15, ty = tid >> 4;
    const int m0 = blockIdx.y << 6;
    const int n0 = blockIdx.x << 6;
    float acc[4][4] = {};

    for (int k0 = 0; k0 < DM_; k0 += 16) {
        #pragma unroll
        for (int i = 0; i < 4; i++) {
            int e = tid + (i << 8);
            Xs[e & 15][e >> 4] = X[(m0 + (e >> 4)) * DM_ + k0 + (e & 15)];
        }
        #pragma unroll
        for (int i = 0; i < 4; i++) {
            int e = tid + (i << 8);
            Ws[e >> 6][e & 63] = W[(k0 + (e >> 6)) * DM_ + n0 + (e & 63)];
        }
        __syncthreads();
        #pragma unroll
        for (int kk = 0; kk < 16; kk++) {
            float4 av = *(const float4*)&Xs[kk][ty << 2];
            float4 bv = *(const float4*)&Ws[kk][tx << 2];
            float a[4] = {av.x, av.y, av.z, av.w};
            float b[4] = {bv.x, bv.y, bv.z, bv.w};
            #pragma unroll
            for (int i = 0; i < 4; i++)
                #pragma unroll
                for (int j = 0; j < 4; j++)
                    acc[i][j] += a[i] * b[j];
        }
        __syncthreads();
    }

    #pragma unroll
    for (int i = 0; i < 4; i++) {
        int m = m0 + (ty << 2) + i;
        #pragma unroll
        for (int j = 0; j < 4; j++) {
            int n = n0 + (tx << 2) + j;
            float v = acc[i][j] + bias[n];
            if (permute) {
                int bb = m >> 11;      // m / S_
                int s  = m & (S_ - 1);
                int h  = n >> 6;       // n / D_
                int d  = n & 63;
                out[(((bb * H_ + h) * S_) + s) * D_ + d] = v;
            } else {
                out[m * DM_ + n] = v;
            }
        }
    }
}

// ---------------------------------------------------------------------------
// Flash-style attention with relative-position bias + bucketed rel_v term.
// One block per (bh, 64-row q-tile). 256 threads (16x16), 4x4 microkernel.
// ---------------------------------------------------------------------------
struct AttnSmem {
    float Qt[64][68];   // Q transposed [d][r]
    float Kt[64][68];   // K transposed [d][c]
    float Pst[64][68];  // P transposed [c][r]
    float Vs[64][64];   // V straight   [c][d]
    float qrel[64][NB_];
    float rks[NB_][64];
    float rvs[NB_][64];
};

__global__ __launch_bounds__(256, 2) void attn_kernel(
    const float* __restrict__ rel_k, const float* __restrict__ rel_v)
{
    extern __shared__ char smem_raw[];
    AttnSmem& sm = *reinterpret_cast<AttnSmem*>(smem_raw);
    const int tid = threadIdx.x;
    const int tx = tid & 15, ty = tid >> 4;
    const int q0 = blockIdx.x << 6;
    const int bh = blockIdx.y;
    const float* qbase = g_q + (size_t)bh * S_ * D_;
    const float* kbase = g_k + (size_t)bh * S_ * D_;
    const float* vbase = g_v + (size_t)bh * S_ * D_;

    // Load Q tile transposed; rel tables
    for (int e4 = tid; e4 < 1024; e4 += 256) {
        int r = e4 >> 4, d0 = (e4 & 15) << 2;
        float4 v = *(const float4*)&qbase[(q0 + r) * D_ + d0];
        sm.Qt[d0 + 0][r] = v.x; sm.Qt[d0 + 1][r] = v.y;
        sm.Qt[d0 + 2][r] = v.z; sm.Qt[d0 + 3][r] = v.w;
    }
    for (int t = tid; t < NB_ * 64; t += 256) {
        sm.rks[t >> 6][t & 63] = rel_k[t];
        sm.rvs[t >> 6][t & 63] = rel_v[t];
    }
    __syncthreads();

    // qrel[r][j] = q[r] . rel_k[j]   (64 x 5)
    for (int t = tid; t < 64 * NB_; t += 256) {
        int r = t / NB_, jb = t % NB_;
        float sacc = 0.f;
        #pragma unroll 8
        for (int d = 0; d < 64; d++) sacc += sm.Qt[d][r] * sm.rks[jb][d];
        sm.qrel[r][jb] = sacc;
    }
    // visibility of qrel guaranteed by the sync at top of first k-tile iter

    float O[4][4] = {};
    float bsum[4][NB_] = {};
    float m_i[4], l_i[4];
    #pragma unroll
    for (int i = 0; i < 4; i++) { m_i[i] = -1e30f; l_i[i] = 0.f; }

    for (int kt = 0; kt < S_ / 64; kt++) {
        const int k0 = kt << 6;
        __syncthreads();   // previous iter done with Kt/Vs/Pst; qrel visible on iter 0
        for (int e4 = tid; e4 < 1024; e4 += 256) {
            int c = e4 >> 4, d0 = (e4 & 15) << 2;
            float4 kv = *(const float4*)&kbase[(k0 + c) * D_ + d0];
            sm.Kt[d0 + 0][c] = kv.x; sm.Kt[d0 + 1][c] = kv.y;
            sm.Kt[d0 + 2][c] = kv.z; sm.Kt[d0 + 3][c] = kv.w;
            float4 vv = *(const float4*)&vbase[(k0 + c) * D_ + d0];
            *(float4*)&sm.Vs[c][d0] = vv;
        }
        __syncthreads();

        // S = Q @ K^T  (64x64x64)
        float s[4][4] = {};
        #pragma unroll 8
        for (int d = 0; d < 64; d++) {
            float4 av = *(const float4*)&sm.Qt[d][ty << 2];
            float4 bv = *(const float4*)&sm.Kt[d][tx << 2];
            float a[4] = {av.x, av.y, av.z, av.w};
            float b[4] = {bv.x, bv.y, bv.z, bv.w};
            #pragma unroll
            for (int i = 0; i < 4; i++)
                #pragma unroll
                for (int j = 0; j < 4; j++)
                    s[i][j] += a[i] * b[j];
        }

        // bias + scale + online softmax (row group = 16 lanes of a half-warp)
        #pragma unroll
        for (int i = 0; i < 4; i++) {
            const int r  = (ty << 2) + i;
            const int rg = q0 + r;
            float mx = -1e30f;
            #pragma unroll
            for (int j = 0; j < 4; j++) {
                int cg = k0 + (tx << 2) + j;
                int jb = min(max(cg - rg, -2), 2) + 2;
                float val = (s[i][j] + sm.qrel[r][jb]) * SCALE_;
                s[i][j] = val;
                mx = fmaxf(mx, val);
            }
            #pragma unroll
            for (int o = 8; o >= 1; o >>= 1)
                mx = fmaxf(mx, __shfl_xor_sync(0xffffffffu, mx, o));
            float m_new = fmaxf(m_i[i], mx);
            float scl = exp2f((m_i[i] - m_new) * LOG2E_);
            m_i[i] = m_new;
            float rs = 0.f;
            #pragma unroll
            for (int j = 0; j < 4; j++) {
                float p = exp2f((s[i][j] - m_new) * LOG2E_);
                s[i][j] = p;
                rs += p;
            }
            #pragma unroll
            for (int o = 8; o >= 1; o >>= 1)
                rs += __shfl_xor_sync(0xffffffffu, rs, o);
            l_i[i] = l_i[i] * scl + rs;
            #pragma unroll
            for (int j = 0; j < 4; j++) O[i][j] *= scl;
            #pragma unroll
            for (int jb = 0; jb < NB_; jb++) bsum[i][jb] *= scl;
            #pragma unroll
            for (int j = 0; j < 4; j++) {
                int cg = k0 + (tx << 2) + j;
                int jb = min(max(cg - rg, -2), 2) + 2;
                bsum[i][jb] += s[i][j];
            }
        }

        // Write P transposed
        #pragma unroll
        for (int j = 0; j < 4; j++)
            #pragma unroll
            for (int i = 0; i < 4; i++)
                sm.Pst[(tx << 2) + j][(ty << 2) + i] = s[i][j];
        __syncthreads();

        // O += P @ V  (64x64x64)
        #pragma unroll 8
        for (int c = 0; c < 64; c++) {
            float4 av = *(const float4*)&sm.Pst[c][ty << 2];
            float4 bv = *(const float4*)&sm.Vs[c][tx << 2];
            float a[4] = {av.x, av.y, av.z, av.w};
            float b[4] = {bv.x, bv.y, bv.z, bv.w};
            #pragma unroll
            for (int i = 0; i < 4; i++)
                #pragma unroll
                for (int j = 0; j < 4; j++)
                    O[i][j] += a[i] * b[j];
        }
    }

    // Reduce bucket sums across the 16-lane row group
    #pragma unroll
    for (int i = 0; i < 4; i++)
        #pragma unroll
        for (int jb = 0; jb < NB_; jb++)
            #pragma unroll
            for (int o = 8; o >= 1; o >>= 1)
                bsum[i][jb] += __shfl_xor_sync(0xffffffffu, bsum[i][jb], o);

    const int bb = bh / H_, h = bh % H_;
    #pragma unroll
    for (int i = 0; i < 4; i++) {
        float inv = 1.f / l_i[i];
        int sg = q0 + (ty << 2) + i;
        #pragma unroll
        for (int j = 0; j < 4; j++) {
            int d = (tx << 2) + j;
            float o2 = 0.f;
            #pragma unroll
            for (int jb = 0; jb < NB_; jb++) o2 += bsum[i][jb] * sm.rvs[jb][d];
            g_att[((bb * S_ + sg) * H_ + h) * D_ + d] = (O[i][j] + o2) * inv;
        }
    }
}

// ---------------------------------------------------------------------------
extern "C" void kernel_launch(void* const* d_in, const int* in_sizes, int n_in,
                              void* d_out, int out_size) {
    const float* x    = (const float*)d_in[0];
    const float* Wq   = (const float*)d_in[1];
    const float* bq   = (const float*)d_in[2];
    const float* Wk   = (const float*)d_in[3];
    const float* bk   = (const float*)d_in[4];
    const float* Wv   = (const float*)d_in[5];
    const float* bv   = (const float*)d_in[6];
    const float* Wo   = (const float*)d_in[7];
    const float* bo   = (const float*)d_in[8];
    const float* relk = (const float*)d_in[9];
    const float* relv = (const float*)d_in[10];
    float* out = (float*)d_out;

    float *gq, *gk, *gv, *gatt;
    cudaGetSymbolAddress((void**)&gq,   g_q);
    cudaGetSymbolAddress((void**)&gk,   g_k);
    cudaGetSymbolAddress((void**)&gv,   g_v);
    cudaGetSymbolAddress((void**)&gatt, g_att);

    cudaFuncSetAttribute(attn_kernel,
                         cudaFuncAttributeMaxDynamicSharedMemorySize,
                         (int)sizeof(AttnSmem));

    dim3 ggrid(DM_ / 64, (B_ * S_) / 64);
    sgemm64<<<ggrid, 256>>>(x, Wq, bq, gq, 1);
    sgemm64<<<ggrid, 256>>>(x, Wk, bk, gk, 1);
    sgemm64<<<ggrid, 256>>>(x, Wv, bv, gv, 1);
    attn_kernel<<<dim3(S_ / 64, B_ * H_), 256, sizeof(AttnSmem)>>>(relk, relv);
    sgemm64<<<ggrid, 256>>>(gatt, Wo, bo, out, 0);
}

// round 3
// speedup vs baseline: 2.8902x; 2.8902x over previous
#include <cuda_runtime.h>

#define B_   2
#define S_   2048
#define DM_  1024
#define H_   16
#define D_   64
#define NB_  5
#define SCALE_ 0.125f
#define LOG2E_ 1.4426950408889634f
#define ALPHA_ (SCALE_ * LOG2E_)

// Static device scratch (allocation-free rule)
__device__ float g_q[B_*H_*S_*D_];
__device__ float g_k[B_*H_*S_*D_];
__device__ float g_v[B_*H_*S_*D_];
__device__ float g_att[B_*S_*DM_];

// ---------------------------------------------------------------------------
// helpers
// ---------------------------------------------------------------------------
__device__ __forceinline__ unsigned f2tf(float x) {
    unsigned r;
    asm("cvt.rna.tf32.f32 %0, %1;" : "=r"(r) : "f"(x));
    return r;
}

__device__ __forceinline__ void mma8(float* c, const unsigned* a, const unsigned* b) {
    asm volatile(
        "mma.sync.aligned.m16n8k8.row.col.f32.tf32.tf32.f32 "
        "{%0,%1,%2,%3}, {%4,%5,%6,%7}, {%8,%9}, {%0,%1,%2,%3};"
        : "+f"(c[0]), "+f"(c[1]), "+f"(c[2]), "+f"(c[3])
        : "r"(a[0]), "r"(a[1]), "r"(a[2]), "r"(a[3]), "r"(b[0]), "r"(b[1]));
}

// exp2 on FMA pipe: degree-6 Taylor on fractional part + exponent splice.
// Valid for y <= 0 (softmax domain); clamps at -28 (2^-28 ~ 4e-9, negligible).
__device__ __forceinline__ float exp2p(float y) {
    y = fmaxf(y, -28.f);
    float fl = floorf(y);
    float f = y - fl;
    float p = fmaf(1.5403530e-4f, f, 1.3333558e-3f);
    p = fmaf(p, f, 9.6181291e-3f);
    p = fmaf(p, f, 5.5504109e-2f);
    p = fmaf(p, f, 2.4022651e-1f);
    p = fmaf(p, f, 6.9314718e-1f);
    p = fmaf(p, f, 1.0f);
    return p * __int_as_float(((int)fl + 127) << 23);
}

// ---------------------------------------------------------------------------
// TF32 tensor-core GEMM: out = X @ W + bias.  X:[4096,1024], W:[1024,1024].
// Block 128x128, 256 threads (8 warps, warp tile 64x32). K-step 32.
// permute=1 -> BHSD layout for q/k/v; permute=0 -> plain row-major.
// ---------------------------------------------------------------------------
__global__ __launch_bounds__(256) void gemm_tf32(
    const float* __restrict__ X, const float* __restrict__ W,
    const float* __restrict__ bias, float* __restrict__ out, int permute)
{
    __shared__ unsigned Xs[128][36];   // [row][k]  ld 36 (== 4 mod 32): conflict-free A loads
    __shared__ unsigned Ws[32][132];   // [k][col]  ld 132

    const int tid  = threadIdx.x;
    const int lane = tid & 31, wid = tid >> 5;
    const int qd = lane >> 2, lr = lane & 3;     // group-id, thread-in-group
    const int wm = wid >> 2, wn = wid & 3;       // warp grid 2x4
    const int m0 = blockIdx.y << 7;
    const int n0 = blockIdx.x << 7;

    float acc[4][4][4] = {};

    for (int k0 = 0; k0 < DM_; k0 += 32) {
        __syncthreads();
        #pragma unroll
        for (int it = 0; it < 4; it++) {       // X tile: 128x32 = 1024 float4
            int lin = tid + (it << 8);
            int r = lin >> 3, c4 = (lin & 7) << 2;
            float4 v = *(const float4*)&X[(size_t)(m0 + r) * DM_ + k0 + c4];
            uint4 u = make_uint4(f2tf(v.x), f2tf(v.y), f2tf(v.z), f2tf(v.w));
            *(uint4*)&Xs[r][c4] = u;
        }
        #pragma unroll
        for (int it = 0; it < 4; it++) {       // W tile: 32x128
            int lin = tid + (it << 8);
            int k = lin >> 5, c4 = (lin & 31) << 2;
            float4 v = *(const float4*)&W[(size_t)(k0 + k) * DM_ + n0 + c4];
            uint4 u = make_uint4(f2tf(v.x), f2tf(v.y), f2tf(v.z), f2tf(v.w));
            *(uint4*)&Ws[k][c4] = u;
        }
        __syncthreads();

        #pragma unroll
        for (int ks = 0; ks < 4; ks++) {
            int kk = ks << 3;
            unsigned a[4][4], b[4][2];
            #pragma unroll
            for (int mf = 0; mf < 4; mf++) {
                int r = (wm << 6) + (mf << 4) + qd;
                a[mf][0] = Xs[r][kk + lr];
                a[mf][1] = Xs[r + 8][kk + lr];
                a[mf][2] = Xs[r][kk + lr + 4];
                a[mf][3] = Xs[r + 8][kk + lr + 4];
            }
            #pragma unroll
            for (int nf = 0; nf < 4; nf++) {
                int n = (wn << 5) + (nf << 3) + qd;
                b[nf][0] = Ws[kk + lr][n];
                b[nf][1] = Ws[kk + lr + 4][n];
            }
            #pragma unroll
            for (int mf = 0; mf < 4; mf++)
                #pragma unroll
                for (int nf = 0; nf < 4; nf++)
                    mma8(acc[mf][nf], a[mf], b[nf]);
        }
    }

    #pragma unroll
    for (int mf = 0; mf < 4; mf++) {
        #pragma unroll
        for (int nf = 0; nf < 4; nf++) {
            #pragma unroll
            for (int e = 0; e < 4; e++) {
                int m = m0 + (wm << 6) + (mf << 4) + qd + ((e >> 1) << 3);
                int n = n0 + (wn << 5) + (nf << 3) + (lr << 1) + (e & 1);
                float v = acc[mf][nf][e] + bias[n];
                if (permute) {
                    int bb = m >> 11, s = m & (S_ - 1);
                    int h = n >> 6, d = n & 63;
                    out[(((bb * H_ + h) * S_) + s) * D_ + d] = v;
                } else {
                    out[(size_t)m * DM_ + n] = v;
                }
            }
        }
    }
}

// ---------------------------------------------------------------------------
// Flash attention, tf32 tensor cores + poly exp + uniform-bucket fast path.
// 128 threads (4 warps), q-tile 64 (warp = 16 rows), k-tiles of 64.
// ---------------------------------------------------------------------------
struct ASmem {
    float Ks[64][68];       // K tile [kpos][d]  (Q tile during prologue)
    float Vt[64][68];       // V transposed [d][kpos]
    float Pw[4][16][68];    // per-warp P tile
    float qrel[64][8];      // q . rel_k per bucket
    float rks[NB_][64];
    float rvs[NB_][64];
};

__global__ __launch_bounds__(128, 3) void attn_tf32(
    const float* __restrict__ rel_k, const float* __restrict__ rel_v)
{
    extern __shared__ char sraw[];
    ASmem& sm = *reinterpret_cast<ASmem*>(sraw);
    const int tid = threadIdx.x;
    const int lane = tid & 31, wid = tid >> 5;
    const int qd = lane >> 2, lr = lane & 3;
    const int qt = blockIdx.x;
    const int q0 = qt << 6;
    const int bh = blockIdx.y;
    const float* qbase = g_q + (size_t)bh * S_ * D_;
    const float* kbase = g_k + (size_t)bh * S_ * D_;
    const float* vbase = g_v + (size_t)bh * S_ * D_;

    // Prologue: Q tile (tf32-rounded) into Ks; rel tables
    #pragma unroll
    for (int it = 0; it < 8; it++) {
        int lin = tid + (it << 7);
        int r = lin >> 4, c4 = (lin & 15) << 2;
        float4 v = *(const float4*)&qbase[(q0 + r) * D_ + c4];
        uint4 u = make_uint4(f2tf(v.x), f2tf(v.y), f2tf(v.z), f2tf(v.w));
        *(uint4*)&sm.Ks[r][c4] = u;
    }
    for (int t = tid; t < NB_ * 64; t += 128) {
        sm.rks[t >> 6][t & 63] = rel_k[t];
        sm.rvs[t >> 6][t & 63] = rel_v[t];
    }
    __syncthreads();

    // qrel[r][jb] = q[r] . rel_k[jb]
    for (int t = tid; t < 64 * NB_; t += 128) {
        int r = t / NB_, jb = t % NB_;
        float s = 0.f;
        #pragma unroll 8
        for (int d = 0; d < 64; d++) s += sm.Ks[r][d] * sm.rks[jb][d];
        sm.qrel[r][jb] = s;
    }

    // Q fragments into registers (A layout, m16 x k64)
    unsigned qf[8][4];
    const int rl0 = (wid << 4) + qd;
    #pragma unroll
    for (int kf = 0; kf < 8; kf++) {
        qf[kf][0] = __float_as_uint(sm.Ks[rl0][(kf << 3) + lr]);
        qf[kf][1] = __float_as_uint(sm.Ks[rl0 + 8][(kf << 3) + lr]);
        qf[kf][2] = __float_as_uint(sm.Ks[rl0][(kf << 3) + lr + 4]);
        qf[kf][3] = __float_as_uint(sm.Ks[rl0 + 8][(kf << 3) + lr + 4]);
    }
    __syncthreads();

    float O[8][4] = {};
    float m0r = -1e30f, m1r = -1e30f, l0 = 0.f, l1 = 0.f;
    float bs0[NB_] = {}, bs1[NB_] = {};
    const int r0g = q0 + rl0, r1g = r0g + 8;

    for (int kt = 0; kt < S_ / 64; kt++) {
        const int k0 = kt << 6;
        __syncthreads();
        #pragma unroll
        for (int it = 0; it < 8; it++) {
            int lin = tid + (it << 7);
            int r = lin >> 4, c4 = (lin & 15) << 2;
            float4 kv = *(const float4*)&kbase[(k0 + r) * D_ + c4];
            uint4 ku = make_uint4(f2tf(kv.x), f2tf(kv.y), f2tf(kv.z), f2tf(kv.w));
            *(uint4*)&sm.Ks[r][c4] = ku;
            float4 vv = *(const float4*)&vbase[(k0 + r) * D_ + c4];
            sm.Vt[c4 + 0][r] = __uint_as_float(f2tf(vv.x));
            sm.Vt[c4 + 1][r] = __uint_as_float(f2tf(vv.y));
            sm.Vt[c4 + 2][r] = __uint_as_float(f2tf(vv.z));
            sm.Vt[c4 + 3][r] = __uint_as_float(f2tf(vv.w));
        }
        __syncthreads();

        // S = Q @ K^T
        float s[8][4] = {};
        #pragma unroll
        for (int nf = 0; nf < 8; nf++) {
            #pragma unroll
            for (int kf = 0; kf < 8; kf++) {
                unsigned b[2];
                b[0] = __float_as_uint(sm.Ks[(nf << 3) + qd][(kf << 3) + lr]);
                b[1] = __float_as_uint(sm.Ks[(nf << 3) + qd][(kf << 3) + lr + 4]);
                mma8(s[nf], qf[kf], b);
            }
        }

        // bias + online softmax
        float mnew0, mnew1, rs0 = 0.f, rs1 = 0.f;
        bool mixed = (kt + 1 >= qt) && (kt <= qt + 1);
        if (!mixed) {
            const int bkt = (kt > qt) ? 4 : 0;
            float qb0 = sm.qrel[rl0][bkt] * ALPHA_;
            float qb1 = sm.qrel[rl0 + 8][bkt] * ALPHA_;
            float mx0 = -1e30f, mx1 = -1e30f;
            #pragma unroll
            for (int nf = 0; nf < 8; nf++) {
                mx0 = fmaxf(mx0, fmaxf(s[nf][0], s[nf][1]));
                mx1 = fmaxf(mx1, fmaxf(s[nf][2], s[nf][3]));
            }
            mx0 = fmaxf(mx0, __shfl_xor_sync(0xffffffffu, mx0, 1));
            mx0 = fmaxf(mx0, __shfl_xor_sync(0xffffffffu, mx0, 2));
            mx1 = fmaxf(mx1, __shfl_xor_sync(0xffffffffu, mx1, 1));
            mx1 = fmaxf(mx1, __shfl_xor_sync(0xffffffffu, mx1, 2));
            mnew0 = fmaxf(m0r, fmaf(mx0, ALPHA_, qb0));
            mnew1 = fmaxf(m1r, fmaf(mx1, ALPHA_, qb1));
            float sc0 = exp2p(m0r - mnew0), sc1 = exp2p(m1r - mnew1);
            m0r = mnew0; m1r = mnew1;
            l0 *= sc0; l1 *= sc1;
            #pragma unroll
            for (int jb = 0; jb < NB_; jb++) { bs0[jb] *= sc0; bs1[jb] *= sc1; }
            #pragma unroll
            for (int nf = 0; nf < 8; nf++) {
                O[nf][0] *= sc0; O[nf][1] *= sc0; O[nf][2] *= sc1; O[nf][3] *= sc1;
            }
            float c0 = qb0 - mnew0, c1 = qb1 - mnew1;
            #pragma unroll
            for (int nf = 0; nf < 8; nf++) {
                float p0 = exp2p(fmaf(s[nf][0], ALPHA_, c0));
                float p1 = exp2p(fmaf(s[nf][1], ALPHA_, c0));
                float p2 = exp2p(fmaf(s[nf][2], ALPHA_, c1));
                float p3 = exp2p(fmaf(s[nf][3], ALPHA_, c1));
                s[nf][0] = p0; s[nf][1] = p1; s[nf][2] = p2; s[nf][3] = p3;
                rs0 += p0 + p1; rs1 += p2 + p3;
            }
            l0 += rs0; l1 += rs1;
            bs0[bkt] += rs0; bs1[bkt] += rs1;
        } else {
            float mx0 = -1e30f, mx1 = -1e30f;
            int jbs[8][4];
            #pragma unroll
            for (int nf = 0; nf < 8; nf++) {
                #pragma unroll
                for (int e = 0; e < 4; e++) {
                    int kp = k0 + (nf << 3) + (lr << 1) + (e & 1);
                    int rg = (e < 2) ? r0g : r1g;
                    int rl = (e < 2) ? rl0 : rl0 + 8;
                    int jb = min(max(kp - rg, -2), 2) + 2;
                    jbs[nf][e] = jb;
                    float y = (s[nf][e] + sm.qrel[rl][jb]) * ALPHA_;
                    s[nf][e] = y;
                    if (e < 2) mx0 = fmaxf(mx0, y); else mx1 = fmaxf(mx1, y);
                }
            }
            mx0 = fmaxf(mx0, __shfl_xor_sync(0xffffffffu, mx0, 1));
            mx0 = fmaxf(mx0, __shfl_xor_sync(0xffffffffu, mx0, 2));
            mx1 = fmaxf(mx1, __shfl_xor_sync(0xffffffffu, mx1, 1));
            mx1 = fmaxf(mx1, __shfl_xor_sync(0xffffffffu, mx1, 2));
            mnew0 = fmaxf(m0r, mx0);
            mnew1 = fmaxf(m1r, mx1);
            float sc0 = exp2p(m0r - mnew0), sc1 = exp2p(m1r - mnew1);
            m0r = mnew0; m1r = mnew1;
            l0 *= sc0; l1 *= sc1;
            #pragma unroll
            for (int jb = 0; jb < NB_; jb++) { bs0[jb] *= sc0; bs1[jb] *= sc1; }
            #pragma unroll
            for (int nf = 0; nf < 8; nf++) {
                O[nf][0] *= sc0; O[nf][1] *= sc0; O[nf][2] *= sc1; O[nf][3] *= sc1;
            }
            #pragma unroll
            for (int nf = 0; nf < 8; nf++) {
                #pragma unroll
                for (int e = 0; e < 4; e++) {
                    float p = exp2p(s[nf][e] - ((e < 2) ? mnew0 : mnew1));
                    s[nf][e] = p;
                    if (e < 2) { rs0 += p; bs0[jbs[nf][e]] += p; }
                    else       { rs1 += p; bs1[jbs[nf][e]] += p; }
                }
            }
            l0 += rs0; l1 += rs1;
        }

        // store P (tf32) into warp-private smem
        #pragma unroll
        for (int nf = 0; nf < 8; nf++) {
            int c = (nf << 3) + (lr << 1);
            sm.Pw[wid][qd][c]         = __uint_as_float(f2tf(s[nf][0]));
            sm.Pw[wid][qd][c + 1]     = __uint_as_float(f2tf(s[nf][1]));
            sm.Pw[wid][qd + 8][c]     = __uint_as_float(f2tf(s[nf][2]));
            sm.Pw[wid][qd + 8][c + 1] = __uint_as_float(f2tf(s[nf][3]));
        }
        __syncwarp();

        // O += P @ V
        #pragma unroll
        for (int kf = 0; kf < 8; kf++) {
            unsigned a[4];
            a[0] = __float_as_uint(sm.Pw[wid][qd][(kf << 3) + lr]);
            a[1] = __float_as_uint(sm.Pw[wid][qd + 8][(kf << 3) + lr]);
            a[2] = __float_as_uint(sm.Pw[wid][qd][(kf << 3) + lr + 4]);
            a[3] = __float_as_uint(sm.Pw[wid][qd + 8][(kf << 3) + lr + 4]);
            #pragma unroll
            for (int nf = 0; nf < 8; nf++) {
                unsigned b[2];
                b[0] = __float_as_uint(sm.Vt[(nf << 3) + qd][(kf << 3) + lr]);
                b[1] = __float_as_uint(sm.Vt[(nf << 3) + qd][(kf << 3) + lr + 4]);
                mma8(O[nf], a, b);
            }
        }
    }

    // reduce per-lane partials across the quad
    #pragma unroll
    for (int o = 1; o <= 2; o <<= 1) {
        l0 += __shfl_xor_sync(0xffffffffu, l0, o);
        l1 += __shfl_xor_sync(0xffffffffu, l1, o);
        #pragma unroll
        for (int jb = 0; jb < NB_; jb++) {
            bs0[jb] += __shfl_xor_sync(0xffffffffu, bs0[jb], o);
            bs1[jb] += __shfl_xor_sync(0xffffffffu, bs1[jb], o);
        }
    }
    float inv0 = 1.f / l0, inv1 = 1.f / l1;

    const int bb = bh / H_, h = bh % H_;
    #pragma unroll
    for (int nf = 0; nf < 8; nf++) {
        int d0 = (nf << 3) + (lr << 1);
        float o200 = 0.f, o201 = 0.f, o210 = 0.f, o211 = 0.f;
        #pragma unroll
        for (int jb = 0; jb < NB_; jb++) {
            float rv0 = sm.rvs[jb][d0], rv1 = sm.rvs[jb][d0 + 1];
            o200 += bs0[jb] * rv0; o201 += bs0[jb] * rv1;
            o210 += bs1[jb] * rv0; o211 += bs1[jb] * rv1;
        }
        float2 w0 = make_float2((O[nf][0] + o200) * inv0, (O[nf][1] + o201) * inv0);
        float2 w1 = make_float2((O[nf][2] + o210) * inv1, (O[nf][3] + o211) * inv1);
        *(float2*)&g_att[(((size_t)bb * S_ + r0g) * H_ + h) * D_ + d0] = w0;
        *(float2*)&g_att[(((size_t)bb * S_ + r1g) * H_ + h) * D_ + d0] = w1;
    }
}

// ---------------------------------------------------------------------------
extern "C" void kernel_launch(void* const* d_in, const int* in_sizes, int n_in,
                              void* d_out, int out_size) {
    const float* x    = (const float*)d_in[0];
    const float* Wq   = (const float*)d_in[1];
    const float* bq   = (const float*)d_in[2];
    const float* Wk   = (const float*)d_in[3];
    const float* bk   = (const float*)d_in[4];
    const float* Wv   = (const float*)d_in[5];
    const float* bv   = (const float*)d_in[6];
    const float* Wo   = (const float*)d_in[7];
    const float* bo   = (const float*)d_in[8];
    const float* relk = (const float*)d_in[9];
    const float* relv = (const float*)d_in[10];
    float* out = (float*)d_out;

    float *gq, *gk, *gv, *gatt;
    cudaGetSymbolAddress((void**)&gq,   g_q);
    cudaGetSymbolAddress((void**)&gk,   g_k);
    cudaGetSymbolAddress((void**)&gv,   g_v);
    cudaGetSymbolAddress((void**)&gatt, g_att);

    cudaFuncSetAttribute(attn_tf32,
                         cudaFuncAttributeMaxDynamicSharedMemorySize,
                         (int)sizeof(ASmem));

    dim3 ggrid(DM_ / 128, (B_ * S_) / 128);
    gemm_tf32<<<ggrid, 256>>>(x, Wq, bq, gq, 1);
    gemm_tf32<<<ggrid, 256>>>(x, Wk, bk, gk, 1);
    gemm_tf32<<<ggrid, 256>>>(x, Wv, bv, gv, 1);
    attn_tf32<<<dim3(S_ / 64, B_ * H_), 128, sizeof(ASmem)>>>(relk, relv);
    gemm_tf32<<<ggrid, 256>>>(gatt, Wo, bo, out, 0);
}

// round 4
// speedup vs baseline: 3.2644x; 1.1295x over previous
#include <cuda_runtime.h>

#define B_   2
#define S_   2048
#define DM_  1024
#define H_   16
#define D_   64
#define NB_  5
#define SCALE_ 0.125f
#define LOG2E_ 1.4426950408889634f
#define ALPHA_ (SCALE_ * LOG2E_)

// Static device scratch (allocation-free rule)
__device__ float g_q[B_*H_*S_*D_];
__device__ float g_k[B_*H_*S_*D_];
__device__ float g_v[B_*H_*S_*D_];
__device__ float g_att[B_*S_*DM_];

// ---------------------------------------------------------------------------
// helpers
// ---------------------------------------------------------------------------
__device__ __forceinline__ unsigned f2tf(float x) {
    unsigned r;
    asm("cvt.rna.tf32.f32 %0, %1;" : "=r"(r) : "f"(x));
    return r;
}

__device__ __forceinline__ void mma8(float* c, const unsigned* a, const unsigned* b) {
    asm volatile(
        "mma.sync.aligned.m16n8k8.row.col.f32.tf32.tf32.f32 "
        "{%0,%1,%2,%3}, {%4,%5,%6,%7}, {%8,%9}, {%0,%1,%2,%3};"
        : "+f"(c[0]), "+f"(c[1]), "+f"(c[2]), "+f"(c[3])
        : "r"(a[0]), "r"(a[1]), "r"(a[2]), "r"(a[3]), "r"(b[0]), "r"(b[1]));
}

// exp2 on FMA/ALU pipes only. Valid for y <= 0 (softmax domain); clamps at -28.
// Magic-number round-to-nearest; poly on f in [-0.5, 0.5].
__device__ __forceinline__ float exp2p(float y) {
    y = fmaxf(y, -28.f);
    float t = y + 12582912.0f;           // 1.5 * 2^23
    float fl = t - 12582912.0f;
    float f = y - fl;                    // [-0.5, 0.5] exact
    float p = fmaf(1.5403530e-4f, f, 1.3333558e-3f);
    p = fmaf(p, f, 9.6181291e-3f);
    p = fmaf(p, f, 5.5504109e-2f);
    p = fmaf(p, f, 2.4022651e-1f);
    p = fmaf(p, f, 6.9314718e-1f);
    p = fmaf(p, f, 1.0f);
    // low 23 bits of t encode round(y) + 0x400000
    int e = ((__float_as_int(t) & 0x7FFFFF) - 0x400000 + 127) << 23;
    return p * __int_as_float(e);
}

// ---------------------------------------------------------------------------
// TF32 tensor-core GEMM with register prefetch: out = X @ W + bias.
// X:[4096,1024], W:[1024,1024]. Block 128x128, 256 thr, k-step 32.
// ---------------------------------------------------------------------------
__global__ __launch_bounds__(256) void gemm_tf32(
    const float* __restrict__ X, const float* __restrict__ W,
    const float* __restrict__ bias, float* __restrict__ out, int permute)
{
    __shared__ unsigned Xs[128][36];
    __shared__ unsigned Ws[32][132];

    const int tid  = threadIdx.x;
    const int lane = tid & 31, wid = tid >> 5;
    const int qd = lane >> 2, lr = lane & 3;
    const int wm = wid >> 2, wn = wid & 3;
    const int m0 = blockIdx.y << 7;
    const int n0 = blockIdx.x << 7;

    const int xr = tid >> 3, xc = (tid & 7) << 2;       // +32 rows per it
    const int wr = tid >> 5, wc = (tid & 31) << 2;      // +8 k-rows per it

    float4 px[4], pw[4];
    #pragma unroll
    for (int it = 0; it < 4; it++)
        px[it] = *(const float4*)&X[(size_t)(m0 + xr + (it << 5)) * DM_ + xc];
    #pragma unroll
    for (int it = 0; it < 4; it++)
        pw[it] = *(const float4*)&W[(size_t)(wr + (it << 3)) * DM_ + n0 + wc];

    float acc[4][4][4] = {};

    for (int k0 = 0; k0 < DM_; k0 += 32) {
        // store current prefetched tile (tf32-rounded)
        #pragma unroll
        for (int it = 0; it < 4; it++) {
            uint4 u = make_uint4(f2tf(px[it].x), f2tf(px[it].y),
                                 f2tf(px[it].z), f2tf(px[it].w));
            *(uint4*)&Xs[xr + (it << 5)][xc] = u;
        }
        #pragma unroll
        for (int it = 0; it < 4; it++) {
            uint4 u = make_uint4(f2tf(pw[it].x), f2tf(pw[it].y),
                                 f2tf(pw[it].z), f2tf(pw[it].w));
            *(uint4*)&Ws[wr + (it << 3)][wc] = u;
        }
        __syncthreads();

        // prefetch next k-slice while MMAs run
        if (k0 + 32 < DM_) {
            #pragma unroll
            for (int it = 0; it < 4; it++)
                px[it] = *(const float4*)&X[(size_t)(m0 + xr + (it << 5)) * DM_ + k0 + 32 + xc];
            #pragma unroll
            for (int it = 0; it < 4; it++)
                pw[it] = *(const float4*)&W[(size_t)(k0 + 32 + wr + (it << 3)) * DM_ + n0 + wc];
        }

        #pragma unroll
        for (int ks = 0; ks < 4; ks++) {
            int kk = ks << 3;
            unsigned a[4][4], b[4][2];
            #pragma unroll
            for (int mf = 0; mf < 4; mf++) {
                int r = (wm << 6) + (mf << 4) + qd;
                a[mf][0] = Xs[r][kk + lr];
                a[mf][1] = Xs[r + 8][kk + lr];
                a[mf][2] = Xs[r][kk + lr + 4];
                a[mf][3] = Xs[r + 8][kk + lr + 4];
            }
            #pragma unroll
            for (int nf = 0; nf < 4; nf++) {
                int n = (wn << 5) + (nf << 3) + qd;
                b[nf][0] = Ws[kk + lr][n];
                b[nf][1] = Ws[kk + lr + 4][n];
            }
            #pragma unroll
            for (int mf = 0; mf < 4; mf++)
                #pragma unroll
                for (int nf = 0; nf < 4; nf++)
                    mma8(acc[mf][nf], a[mf], b[nf]);
        }
        __syncthreads();
    }

    #pragma unroll
    for (int mf = 0; mf < 4; mf++) {
        #pragma unroll
        for (int nf = 0; nf < 4; nf++) {
            #pragma unroll
            for (int e = 0; e < 4; e++) {
                int m = m0 + (wm << 6) + (mf << 4) + qd + ((e >> 1) << 3);
                int n = n0 + (wn << 5) + (nf << 3) + (lr << 1) + (e & 1);
                float v = acc[mf][nf][e] + bias[n];
                if (permute) {
                    int bb = m >> 11, s = m & (S_ - 1);
                    int h = n >> 6, d = n & 63;
                    out[(((bb * H_ + h) * S_) + s) * D_ + d] = v;
                } else {
                    out[(size_t)m * DM_ + n] = v;
                }
            }
        }
    }
}

// ---------------------------------------------------------------------------
// Flash attention, tf32 MMA. 128 thr (4 warps), q-tile 64, k-tile 64.
// V stored straight in Vs[64][72] -> conflict-free stores AND B-frag loads.
// ---------------------------------------------------------------------------
struct ASmem {
    float Ks[64][68];       // K tile [kpos][d] (Q during prologue)
    float Vs[64][72];       // V tile [kpos][d], stride 72
    float Pw[4][16][68];    // per-warp P tile
    float qrel[64][8];
    float rks[NB_][64];
    float rvs[NB_][64];
};

__global__ __launch_bounds__(128, 3) void attn_tf32(
    const float* __restrict__ rel_k, const float* __restrict__ rel_v)
{
    extern __shared__ char sraw[];
    ASmem& sm = *reinterpret_cast<ASmem*>(sraw);
    const int tid = threadIdx.x;
    const int lane = tid & 31, wid = tid >> 5;
    const int qd = lane >> 2, lr = lane & 3;
    const int qt = blockIdx.x;
    const int q0 = qt << 6;
    const int bh = blockIdx.y;
    const float* qbase = g_q + (size_t)bh * S_ * D_;
    const float* kbase = g_k + (size_t)bh * S_ * D_;
    const float* vbase = g_v + (size_t)bh * S_ * D_;

    // Prologue: Q tile (tf32-rounded) into Ks; rel tables
    const int lrw = tid >> 4, lc4 = (tid & 15) << 2;
    #pragma unroll
    for (int it = 0; it < 8; it++) {
        int r = lrw + (it << 3);
        float4 v = *(const float4*)&qbase[(q0 + r) * D_ + lc4];
        uint4 u = make_uint4(f2tf(v.x), f2tf(v.y), f2tf(v.z), f2tf(v.w));
        *(uint4*)&sm.Ks[r][lc4] = u;
    }
    for (int t = tid; t < NB_ * 64; t += 128) {
        sm.rks[t >> 6][t & 63] = rel_k[t];
        sm.rvs[t >> 6][t & 63] = rel_v[t];
    }
    __syncthreads();

    // qrel[r][jb] = q[r] . rel_k[jb]
    for (int t = tid; t < 64 * NB_; t += 128) {
        int r = t / NB_, jb = t % NB_;
        float s = 0.f;
        #pragma unroll 8
        for (int d = 0; d < 64; d++) s += sm.Ks[r][d] * sm.rks[jb][d];
        sm.qrel[r][jb] = s;
    }

    // Q fragments into registers (A layout, m16 x k64)
    unsigned qf[8][4];
    const int rl0 = (wid << 4) + qd;
    #pragma unroll
    for (int kf = 0; kf < 8; kf++) {
        qf[kf][0] = __float_as_uint(sm.Ks[rl0][(kf << 3) + lr]);
        qf[kf][1] = __float_as_uint(sm.Ks[rl0 + 8][(kf << 3) + lr]);
        qf[kf][2] = __float_as_uint(sm.Ks[rl0][(kf << 3) + lr + 4]);
        qf[kf][3] = __float_as_uint(sm.Ks[rl0 + 8][(kf << 3) + lr + 4]);
    }
    __syncthreads();

    float O[8][4] = {};
    float m0r = -1e30f, m1r = -1e30f, l0 = 0.f, l1 = 0.f;
    float bs0[NB_] = {}, bs1[NB_] = {};
    const int r0g = q0 + rl0, r1g = r0g + 8;

    for (int kt = 0; kt < S_ / 64; kt++) {
        const int k0 = kt << 6;
        __syncthreads();
        #pragma unroll
        for (int it = 0; it < 8; it++) {
            int r = lrw + (it << 3);
            float4 kv = *(const float4*)&kbase[(k0 + r) * D_ + lc4];
            uint4 ku = make_uint4(f2tf(kv.x), f2tf(kv.y), f2tf(kv.z), f2tf(kv.w));
            *(uint4*)&sm.Ks[r][lc4] = ku;
            float4 vv = *(const float4*)&vbase[(k0 + r) * D_ + lc4];
            uint4 vu = make_uint4(f2tf(vv.x), f2tf(vv.y), f2tf(vv.z), f2tf(vv.w));
            *(uint4*)&sm.Vs[r][lc4] = vu;
        }
        __syncthreads();

        // S = Q @ K^T   (kf outer -> 8 independent accumulators inner)
        float s[8][4] = {};
        #pragma unroll
        for (int kf = 0; kf < 8; kf++) {
            #pragma unroll
            for (int nf = 0; nf < 8; nf++) {
                unsigned b[2];
                b[0] = __float_as_uint(sm.Ks[(nf << 3) + qd][(kf << 3) + lr]);
                b[1] = __float_as_uint(sm.Ks[(nf << 3) + qd][(kf << 3) + lr + 4]);
                mma8(s[nf], qf[kf], b);
            }
        }

        // bias + online softmax
        float rs0 = 0.f, rs1 = 0.f;
        bool mixed = (kt + 1 >= qt) && (kt <= qt + 1);
        if (!mixed) {
            const int bkt = (kt > qt) ? 4 : 0;
            float qb0 = sm.qrel[rl0][bkt] * ALPHA_;
            float qb1 = sm.qrel[rl0 + 8][bkt] * ALPHA_;
            float mx0 = -1e30f, mx1 = -1e30f;
            #pragma unroll
            for (int nf = 0; nf < 8; nf++) {
                mx0 = fmaxf(mx0, fmaxf(s[nf][0], s[nf][1]));
                mx1 = fmaxf(mx1, fmaxf(s[nf][2], s[nf][3]));
            }
            mx0 = fmaxf(mx0, __shfl_xor_sync(0xffffffffu, mx0, 1));
            mx0 = fmaxf(mx0, __shfl_xor_sync(0xffffffffu, mx0, 2));
            mx1 = fmaxf(mx1, __shfl_xor_sync(0xffffffffu, mx1, 1));
            mx1 = fmaxf(mx1, __shfl_xor_sync(0xffffffffu, mx1, 2));
            float mnew0 = fmaxf(m0r, fmaf(mx0, ALPHA_, qb0));
            float mnew1 = fmaxf(m1r, fmaf(mx1, ALPHA_, qb1));
            if (__any_sync(0xffffffffu, (mnew0 > m0r) | (mnew1 > m1r))) {
                float sc0 = exp2p(m0r - mnew0), sc1 = exp2p(m1r - mnew1);
                l0 *= sc0; l1 *= sc1;
                #pragma unroll
                for (int jb = 0; jb < NB_; jb++) { bs0[jb] *= sc0; bs1[jb] *= sc1; }
                #pragma unroll
                for (int nf = 0; nf < 8; nf++) {
                    O[nf][0] *= sc0; O[nf][1] *= sc0; O[nf][2] *= sc1; O[nf][3] *= sc1;
                }
            }
            m0r = mnew0; m1r = mnew1;
            float c0 = qb0 - mnew0, c1 = qb1 - mnew1;
            #pragma unroll
            for (int nf = 0; nf < 8; nf++) {
                float p0 = exp2p(fmaf(s[nf][0], ALPHA_, c0));
                float p1 = exp2p(fmaf(s[nf][1], ALPHA_, c0));
                float p2 = exp2p(fmaf(s[nf][2], ALPHA_, c1));
                float p3 = exp2p(fmaf(s[nf][3], ALPHA_, c1));
                s[nf][0] = p0; s[nf][1] = p1; s[nf][2] = p2; s[nf][3] = p3;
                rs0 += p0 + p1; rs1 += p2 + p3;
            }
            l0 += rs0; l1 += rs1;
            bs0[bkt] += rs0; bs1[bkt] += rs1;
        } else {
            float mx0 = -1e30f, mx1 = -1e30f;
            int jbs[8][4];
            #pragma unroll
            for (int nf = 0; nf < 8; nf++) {
                #pragma unroll
                for (int e = 0; e < 4; e++) {
                    int kp = k0 + (nf << 3) + (lr << 1) + (e & 1);
                    int rg = (e < 2) ? r0g : r1g;
                    int rl = (e < 2) ? rl0 : rl0 + 8;
                    int jb = min(max(kp - rg, -2), 2) + 2;
                    jbs[nf][e] = jb;
                    float y = (s[nf][e] + sm.qrel[rl][jb]) * ALPHA_;
                    s[nf][e] = y;
                    if (e < 2) mx0 = fmaxf(mx0, y); else mx1 = fmaxf(mx1, y);
                }
            }
            mx0 = fmaxf(mx0, __shfl_xor_sync(0xffffffffu, mx0, 1));
            mx0 = fmaxf(mx0, __shfl_xor_sync(0xffffffffu, mx0, 2));
            mx1 = fmaxf(mx1, __shfl_xor_sync(0xffffffffu, mx1, 1));
            mx1 = fmaxf(mx1, __shfl_xor_sync(0xffffffffu, mx1, 2));
            float mnew0 = fmaxf(m0r, mx0);
            float mnew1 = fmaxf(m1r, mx1);
            float sc0 = exp2p(m0r - mnew0), sc1 = exp2p(m1r - mnew1);
            m0r = mnew0; m1r = mnew1;
            l0 *= sc0; l1 *= sc1;
            #pragma unroll
            for (int jb = 0; jb < NB_; jb++) { bs0[jb] *= sc0; bs1[jb] *= sc1; }
            #pragma unroll
            for (int nf = 0; nf < 8; nf++) {
                O[nf][0] *= sc0; O[nf][1] *= sc0; O[nf][2] *= sc1; O[nf][3] *= sc1;
            }
            #pragma unroll
            for (int nf = 0; nf < 8; nf++) {
                #pragma unroll
                for (int e = 0; e < 4; e++) {
                    float p = exp2p(s[nf][e] - ((e < 2) ? m0r : m1r));
                    s[nf][e] = p;
                    if (e < 2) { rs0 += p; bs0[jbs[nf][e]] += p; }
                    else       { rs1 += p; bs1[jbs[nf][e]] += p; }
                }
            }
            l0 += rs0; l1 += rs1;
        }

        // P (tf32) -> warp-private smem
        #pragma unroll
        for (int nf = 0; nf < 8; nf++) {
            int c = (nf << 3) + (lr << 1);
            sm.Pw[wid][qd][c]         = __uint_as_float(f2tf(s[nf][0]));
            sm.Pw[wid][qd][c + 1]     = __uint_as_float(f2tf(s[nf][1]));
            sm.Pw[wid][qd + 8][c]     = __uint_as_float(f2tf(s[nf][2]));
            sm.Pw[wid][qd + 8][c + 1] = __uint_as_float(f2tf(s[nf][3]));
        }
        __syncwarp();

        // O += P @ V  (B frags straight from Vs: B[n][k] = V^T via index swap)
        #pragma unroll
        for (int kf = 0; kf < 8; kf++) {
            unsigned a[4];
            a[0] = __float_as_uint(sm.Pw[wid][qd][(kf << 3) + lr]);
            a[1] = __float_as_uint(sm.Pw[wid][qd + 8][(kf << 3) + lr]);
            a[2] = __float_as_uint(sm.Pw[wid][qd][(kf << 3) + lr + 4]);
            a[3] = __float_as_uint(sm.Pw[wid][qd + 8][(kf << 3) + lr + 4]);
            #pragma unroll
            for (int nf = 0; nf < 8; nf++) {
                unsigned b[2];
                b[0] = __float_as_uint(sm.Vs[(kf << 3) + lr][(nf << 3) + qd]);
                b[1] = __float_as_uint(sm.Vs[(kf << 3) + lr + 4][(nf << 3) + qd]);
                mma8(O[nf], a, b);
            }
        }
    }

    // reduce per-lane partials across the quad
    #pragma unroll
    for (int o = 1; o <= 2; o <<= 1) {
        l0 += __shfl_xor_sync(0xffffffffu, l0, o);
        l1 += __shfl_xor_sync(0xffffffffu, l1, o);
        #pragma unroll
        for (int jb = 0; jb < NB_; jb++) {
            bs0[jb] += __shfl_xor_sync(0xffffffffu, bs0[jb], o);
            bs1[jb] += __shfl_xor_sync(0xffffffffu, bs1[jb], o);
        }
    }
    float inv0 = 1.f / l0, inv1 = 1.f / l1;

    const int bb = bh / H_, h = bh % H_;
    #pragma unroll
    for (int nf = 0; nf < 8; nf++) {
        int d0 = (nf << 3) + (lr << 1);
        float o200 = 0.f, o201 = 0.f, o210 = 0.f, o211 = 0.f;
        #pragma unroll
        for (int jb = 0; jb < NB_; jb++) {
            float rv0 = sm.rvs[jb][d0], rv1 = sm.rvs[jb][d0 + 1];
            o200 += bs0[jb] * rv0; o201 += bs0[jb] * rv1;
            o210 += bs1[jb] * rv0; o211 += bs1[jb] * rv1;
        }
        float2 w0 = make_float2((O[nf][0] + o200) * inv0, (O[nf][1] + o201) * inv0);
        float2 w1 = make_float2((O[nf][2] + o210) * inv1, (O[nf][3] + o211) * inv1);
        *(float2*)&g_att[(((size_t)bb * S_ + r0g) * H_ + h) * D_ + d0] = w0;
        *(float2*)&g_att[(((size_t)bb * S_ + r1g) * H_ + h) * D_ + d0] = w1;
    }
}

// ---------------------------------------------------------------------------
extern "C" void kernel_launch(void* const* d_in, const int* in_sizes, int n_in,
                              void* d_out, int out_size) {
    const float* x    = (const float*)d_in[0];
    const float* Wq   = (const float*)d_in[1];
    const float* bq   = (const float*)d_in[2];
    const float* Wk   = (const float*)d_in[3];
    const float* bk   = (const float*)d_in[4];
    const float* Wv   = (const float*)d_in[5];
    const float* bv   = (const float*)d_in[6];
    const float* Wo   = (const float*)d_in[7];
    const float* bo   = (const float*)d_in[8];
    const float* relk = (const float*)d_in[9];
    const float* relv = (const float*)d_in[10];
    float* out = (float*)d_out;

    float *gq, *gk, *gv, *gatt;
    cudaGetSymbolAddress((void**)&gq,   g_q);
    cudaGetSymbolAddress((void**)&gk,   g_k);
    cudaGetSymbolAddress((void**)&gv,   g_v);
    cudaGetSymbolAddress((void**)&gatt, g_att);

    cudaFuncSetAttribute(attn_tf32,
                         cudaFuncAttributeMaxDynamicSharedMemorySize,
                         (int)sizeof(ASmem));

    dim3 ggrid(DM_ / 128, (B_ * S_) / 128);
    gemm_tf32<<<ggrid, 256>>>(x, Wq, bq, gq, 1);
    gemm_tf32<<<ggrid, 256>>>(x, Wk, bk, gk, 1);
    gemm_tf32<<<ggrid, 256>>>(x, Wv, bv, gv, 1);
    attn_tf32<<<dim3(S_ / 64, B_ * H_), 128, sizeof(ASmem)>>>(relk, relv);
    gemm_tf32<<<ggrid, 256>>>(gatt, Wo, bo, out, 0);
}

// round 6
// speedup vs baseline: 3.5171x; 1.0774x over previous
#include <cuda_runtime.h>

#define B_   2
#define S_   2048
#define DM_  1024
#define H_   16
#define D_   64
#define NB_  5
#define SCALE_ 0.125f
#define LOG2E_ 1.4426950408889634f
#define ALPHA_ (SCALE_ * LOG2E_)

// Static device scratch
__device__ float g_q[B_*H_*S_*D_];
__device__ float g_k[B_*H_*S_*D_];
__device__ float g_v[B_*H_*S_*D_];
__device__ float g_att[B_*S_*DM_];
__device__ float g_xr[4096*1024];      // tf32-rounded x
__device__ float g_wr[4][1024*1024];   // tf32-rounded Wq,Wk,Wv,Wo

// ---------------------------------------------------------------------------
__device__ __forceinline__ unsigned f2tf(float x) {
    unsigned r;
    asm("cvt.rna.tf32.f32 %0, %1;" : "=r"(r) : "f"(x));
    return r;
}
__device__ __forceinline__ float f2tff(float x) { return __uint_as_float(f2tf(x)); }

__device__ __forceinline__ void mma8f(float* c, const float* a, float b0f, float b1f) {
    asm volatile(
        "mma.sync.aligned.m16n8k8.row.col.f32.tf32.tf32.f32 "
        "{%0,%1,%2,%3}, {%4,%5,%6,%7}, {%8,%9}, {%0,%1,%2,%3};"
        : "+f"(c[0]), "+f"(c[1]), "+f"(c[2]), "+f"(c[3])
        : "r"(__float_as_uint(a[0])), "r"(__float_as_uint(a[1])),
          "r"(__float_as_uint(a[2])), "r"(__float_as_uint(a[3])),
          "r"(__float_as_uint(b0f)), "r"(__float_as_uint(b1f)));
}

#define CP16(dst_smem, src) \
    asm volatile("cp.async.cg.shared.global [%0], [%1], 16;\n" :: \
        "r"((unsigned)__cvta_generic_to_shared(dst_smem)), "l"(src) : "memory")
#define CP_COMMIT() asm volatile("cp.async.commit_group;\n" ::: "memory")
#define CP_WAIT0()  asm volatile("cp.async.wait_group 0;\n" ::: "memory")

// exp2 on FMA pipe. Valid for y <= 0; clamps at -28.
__device__ __forceinline__ float exp2p(float y) {
    y = fmaxf(y, -28.f);
    float t = y + 12582912.0f;
    float fl = t - 12582912.0f;
    float f = y - fl;
    float p = fmaf(1.5403530e-4f, f, 1.3333558e-3f);
    p = fmaf(p, f, 9.6181291e-3f);
    p = fmaf(p, f, 5.5504109e-2f);
    p = fmaf(p, f, 2.4022651e-1f);
    p = fmaf(p, f, 6.9314718e-1f);
    p = fmaf(p, f, 1.0f);
    int e = ((__float_as_int(t) & 0x7FFFFF) - 0x400000 + 127) << 23;
    return p * __int_as_float(e);
}

// ---------------------------------------------------------------------------
// Pre-pass: tf32-round x and the 4 weight matrices (once, at the source).
// ---------------------------------------------------------------------------
__global__ void round_pass(const float* __restrict__ x,  const float* __restrict__ wq,
                           const float* __restrict__ wk, const float* __restrict__ wv,
                           const float* __restrict__ wo)
{
    const int total = 1048576 + 4 * 262144;   // float4 counts
    for (int i = blockIdx.x * blockDim.x + threadIdx.x; i < total;
         i += gridDim.x * blockDim.x) {
        const float4* src; float4* dst; int off;
        if (i < 1048576) { src = (const float4*)x; dst = (float4*)g_xr; off = i; }
        else {
            int j = i - 1048576; int seg = j >> 18; off = j & 262143;
            const float* s4 = (seg == 0) ? wq : (seg == 1) ? wk : (seg == 2) ? wv : wo;
            src = (const float4*)s4; dst = (float4*)g_wr[seg];
        }
        float4 v = src[off];
        v.x = f2tff(v.x); v.y = f2tff(v.y); v.z = f2tff(v.z); v.w = f2tff(v.w);
        dst[off] = v;
    }
}

// ---------------------------------------------------------------------------
// TF32 GEMM, cp.async double-buffered. Inputs pre-rounded; out = X@W + bias.
// permute=1 -> BHSD layout, output tf32-rounded. permute=0 -> row-major f32.
// ---------------------------------------------------------------------------
struct GSmem {
    float Xs[2][128][36];
    float Ws[2][32][132];
};

__global__ __launch_bounds__(256) void gemm_tf32(
    const float* __restrict__ X, const float* __restrict__ W,
    const float* __restrict__ bias, float* __restrict__ out, int permute)
{
    extern __shared__ char graw[];
    GSmem& sm = *reinterpret_cast<GSmem*>(graw);
    const int tid  = threadIdx.x;
    const int lane = tid & 31, wid = tid >> 5;
    const int qd = lane >> 2, lr = lane & 3;
    const int wm = wid >> 2, wn = wid & 3;
    const int m0 = blockIdx.y << 7;
    const int n0 = blockIdx.x << 7;

    const int xr = tid >> 3, xc = (tid & 7) << 2;
    const int wr = tid >> 5, wc = (tid & 31) << 2;

    auto load_tile = [&](int buf, int k0) {
        #pragma unroll
        for (int it = 0; it < 4; it++)
            CP16(&sm.Xs[buf][xr + (it << 5)][xc],
                 &X[(size_t)(m0 + xr + (it << 5)) * DM_ + k0 + xc]);
        #pragma unroll
        for (int it = 0; it < 4; it++)
            CP16(&sm.Ws[buf][wr + (it << 3)][wc],
                 &W[(size_t)(k0 + wr + (it << 3)) * DM_ + n0 + wc]);
    };

    load_tile(0, 0);
    CP_COMMIT();

    float acc[4][4][4] = {};

    for (int kt = 0; kt < DM_ / 32; kt++) {
        const int buf = kt & 1;
        CP_WAIT0();
        __syncthreads();
        if (kt + 1 < DM_ / 32) { load_tile(buf ^ 1, (kt + 1) << 5); CP_COMMIT(); }

        #pragma unroll
        for (int ks = 0; ks < 4; ks++) {
            int kk = ks << 3;
            float a[4][4], b[4][2];
            #pragma unroll
            for (int mf = 0; mf < 4; mf++) {
                int r = (wm << 6) + (mf << 4) + qd;
                a[mf][0] = sm.Xs[buf][r][kk + lr];
                a[mf][1] = sm.Xs[buf][r + 8][kk + lr];
                a[mf][2] = sm.Xs[buf][r][kk + lr + 4];
                a[mf][3] = sm.Xs[buf][r + 8][kk + lr + 4];
            }
            #pragma unroll
            for (int nf = 0; nf < 4; nf++) {
                int n = (wn << 5) + (nf << 3) + qd;
                b[nf][0] = sm.Ws[buf][kk + lr][n];
                b[nf][1] = sm.Ws[buf][kk + lr + 4][n];
            }
            #pragma unroll
            for (int mf = 0; mf < 4; mf++)
                #pragma unroll
                for (int nf = 0; nf < 4; nf++)
                    mma8f(acc[mf][nf], a[mf], b[nf][0], b[nf][1]);
        }
    }

    #pragma unroll
    for (int mf = 0; mf < 4; mf++) {
        #pragma unroll
        for (int nf = 0; nf < 4; nf++) {
            #pragma unroll
            for (int e = 0; e < 4; e++) {
                int m = m0 + (wm << 6) + (mf << 4) + qd + ((e >> 1) << 3);
                int n = n0 + (wn << 5) + (nf << 3) + (lr << 1) + (e & 1);
                float v = acc[mf][nf][e] + bias[n];
                if (permute) {
                    int bb = m >> 11, s = m & (S_ - 1);
                    int h = n >> 6, d = n & 63;
                    out[(((bb * H_ + h) * S_) + s) * D_ + d] = f2tff(v);
                } else {
                    out[(size_t)m * DM_ + n] = v;
                }
            }
        }
    }
}

// ---------------------------------------------------------------------------
// Flash attention: q-tile 128, m32/warp (4 warps), k-tile 32, cp.async DB.
// K/V/Q arrive pre-rounded tf32. B-fragments shared across the two m-halves.
// ---------------------------------------------------------------------------
struct ASmem {
    float Ks[2][32][68];
    float Vs[2][32][72];
    float Pw[4][32][72];      // per-warp P; doubles as 128x64 Q staging (stride 72)
    float qrelS[128][8];
    float rkS[NB_][64];
    float rvS[NB_][64];
};

__global__ __launch_bounds__(128, 2) void attn_tf32(
    const float* __restrict__ rel_k, const float* __restrict__ rel_v)
{
    extern __shared__ char sraw[];
    ASmem& sm = *reinterpret_cast<ASmem*>(sraw);
    const int tid = threadIdx.x;
    const int lane = tid & 31, wid = tid >> 5;
    const int qd = lane >> 2, lr = lane & 3;
    const int q0 = blockIdx.x << 7;
    const int bh = blockIdx.y;
    const float* qptr = g_q + (size_t)bh * S_ * D_;
    const float* kptr = g_k + (size_t)bh * S_ * D_;
    const float* vptr = g_v + (size_t)bh * S_ * D_;
    float* PwF = (float*)sm.Pw;   // 128 rows x stride 72 staging view

    auto load_kv = [&](int buf, int k0) {
        #pragma unroll
        for (int it = 0; it < 4; it++) {
            int idx = tid + (it << 7);
            int r = idx >> 4, c4 = (idx & 15) << 2;
            CP16(&sm.Ks[buf][r][c4], &kptr[(size_t)(k0 + r) * D_ + c4]);
            CP16(&sm.Vs[buf][r][c4], &vptr[(size_t)(k0 + r) * D_ + c4]);
        }
    };

    load_kv(0, 0);
    CP_COMMIT();

    // Q staging into Pw area + rel tables
    #pragma unroll
    for (int it = 0; it < 16; it++) {
        int idx = tid + (it << 7);
        int r = idx >> 4, c4 = (idx & 15) << 2;
        float4 v = *(const float4*)&qptr[(size_t)(q0 + r) * D_ + c4];
        *(float4*)&PwF[r * 72 + c4] = v;
    }
    for (int t = tid; t < NB_ * 64; t += 128) {
        sm.rkS[t >> 6][t & 63] = rel_k[t];
        sm.rvS[t >> 6][t & 63] = rel_v[t];
    }
    __syncthreads();

    // Q fragments for both m16 halves (rows wid*32 + 16h + qd (+8))
    const int rw = wid << 5;
    float qf[2][8][4];
    #pragma unroll
    for (int h = 0; h < 2; h++) {
        int r0 = rw + (h << 4) + qd;
        #pragma unroll
        for (int kf = 0; kf < 8; kf++) {
            qf[h][kf][0] = PwF[r0 * 72 + (kf << 3) + lr];
            qf[h][kf][1] = PwF[(r0 + 8) * 72 + (kf << 3) + lr];
            qf[h][kf][2] = PwF[r0 * 72 + (kf << 3) + lr + 4];
            qf[h][kf][3] = PwF[(r0 + 8) * 72 + (kf << 3) + lr + 4];
        }
    }

    // qrel[r][jb] from register Q frags (quad covers all 64 d-cols)
    #pragma unroll
    for (int st = 0; st < 4; st++) {
        int h = st >> 1, rp = st & 1;
        int rloc = rw + (h << 4) + qd + (rp << 3);
        #pragma unroll
        for (int jb = 0; jb < NB_; jb++) {
            float acc = 0.f;
            #pragma unroll
            for (int kf = 0; kf < 8; kf++) {
                acc += qf[h][kf][rp]     * sm.rkS[jb][(kf << 3) + lr];
                acc += qf[h][kf][rp + 2] * sm.rkS[jb][(kf << 3) + lr + 4];
            }
            acc += __shfl_xor_sync(0xffffffffu, acc, 1);
            acc += __shfl_xor_sync(0xffffffffu, acc, 2);
            if (lr == 0) sm.qrelS[rloc][jb] = acc;
        }
    }
    __syncthreads();

    float O0[8][4] = {}, O1[8][4] = {};
    float mS[4], lS[4], bsS[4][NB_] = {};
    #pragma unroll
    for (int st = 0; st < 4; st++) { mS[st] = -1e30f; lS[st] = 0.f; }
    const int rmin = q0 + rw;

    for (int kt = 0; kt < S_ / 32; kt++) {
        const int k0 = kt << 5;
        const int cur = kt & 1;
        CP_WAIT0();
        __syncthreads();
        if (kt + 1 < S_ / 32) { load_kv(cur ^ 1, k0 + 32); CP_COMMIT(); }

        const float (*Kc)[68] = sm.Ks[cur];
        const float (*Vc)[72] = sm.Vs[cur];

        // S = Q @ K^T for both halves, sharing B fragments
        float s0[4][4] = {}, s1[4][4] = {};
        #pragma unroll
        for (int kf = 0; kf < 8; kf++) {
            #pragma unroll
            for (int nf = 0; nf < 4; nf++) {
                float b0 = Kc[(nf << 3) + qd][(kf << 3) + lr];
                float b1 = Kc[(nf << 3) + qd][(kf << 3) + lr + 4];
                mma8f(s0[nf], qf[0][kf], b0, b1);
                mma8f(s1[nf], qf[1][kf], b0, b1);
            }
        }

        bool mixed = (k0 > rmin - 34) && (k0 < rmin + 34);

        // softmax per half
        #pragma unroll
        for (int h = 0; h < 2; h++) {
            float (*s)[4] = (h == 0) ? s0 : s1;
            int stA = h << 1, stB = stA + 1;
            int rlA = rw + (h << 4) + qd;       // local row for state A
            int rgA = q0 + rlA, rgB = rgA + 8;
            float rsA = 0.f, rsB = 0.f;

            if (!mixed) {
                const int bkt = (k0 >= rmin + 34) ? 4 : 0;
                float qbA = sm.qrelS[rlA][bkt] * ALPHA_;
                float qbB = sm.qrelS[rlA + 8][bkt] * ALPHA_;
                float mxA = -1e30f, mxB = -1e30f;
                #pragma unroll
                for (int nf = 0; nf < 4; nf++) {
                    mxA = fmaxf(mxA, fmaxf(s[nf][0], s[nf][1]));
                    mxB = fmaxf(mxB, fmaxf(s[nf][2], s[nf][3]));
                }
                mxA = fmaxf(mxA, __shfl_xor_sync(0xffffffffu, mxA, 1));
                mxA = fmaxf(mxA, __shfl_xor_sync(0xffffffffu, mxA, 2));
                mxB = fmaxf(mxB, __shfl_xor_sync(0xffffffffu, mxB, 1));
                mxB = fmaxf(mxB, __shfl_xor_sync(0xffffffffu, mxB, 2));
                float mnA = fmaxf(mS[stA], fmaf(mxA, ALPHA_, qbA));
                float mnB = fmaxf(mS[stB], fmaf(mxB, ALPHA_, qbB));
                if (__any_sync(0xffffffffu, (mnA > mS[stA]) | (mnB > mS[stB]))) {
                    float scA = exp2p(mS[stA] - mnA), scB = exp2p(mS[stB] - mnB);
                    lS[stA] *= scA; lS[stB] *= scB;
                    #pragma unroll
                    for (int jb = 0; jb < NB_; jb++) { bsS[stA][jb] *= scA; bsS[stB][jb] *= scB; }
                    float (*Oh)[4] = (h == 0) ? O0 : O1;
                    #pragma unroll
                    for (int nf = 0; nf < 8; nf++) {
                        Oh[nf][0] *= scA; Oh[nf][1] *= scA;
                        Oh[nf][2] *= scB; Oh[nf][3] *= scB;
                    }
                }
                mS[stA] = mnA; mS[stB] = mnB;
                float cA = qbA - mnA, cB = qbB - mnB;
                #pragma unroll
                for (int nf = 0; nf < 4; nf++) {
                    float p0 = exp2p(fmaf(s[nf][0], ALPHA_, cA));
                    float p1 = exp2p(fmaf(s[nf][1], ALPHA_, cA));
                    float p2 = exp2p(fmaf(s[nf][2], ALPHA_, cB));
                    float p3 = exp2p(fmaf(s[nf][3], ALPHA_, cB));
                    s[nf][0] = p0; s[nf][1] = p1; s[nf][2] = p2; s[nf][3] = p3;
                    rsA += p0 + p1; rsB += p2 + p3;
                }
                lS[stA] += rsA; lS[stB] += rsB;
                bsS[stA][bkt] += rsA; bsS[stB][bkt] += rsB;
            } else {
                float mxA = -1e30f, mxB = -1e30f;
                int jbs[4][4];
                #pragma unroll
                for (int nf = 0; nf < 4; nf++) {
                    #pragma unroll
                    for (int e = 0; e < 4; e++) {
                        int kp = k0 + (nf << 3) + (lr << 1) + (e & 1);
                        int rg = (e < 2) ? rgA : rgB;
                        int rl = (e < 2) ? rlA : rlA + 8;
                        int jb = min(max(kp - rg, -2), 2) + 2;
                        jbs[nf][e] = jb;
                        float y = (s[nf][e] + sm.qrelS[rl][jb]) * ALPHA_;
                        s[nf][e] = y;
                        if (e < 2) mxA = fmaxf(mxA, y); else mxB = fmaxf(mxB, y);
                    }
                }
                mxA = fmaxf(mxA, __shfl_xor_sync(0xffffffffu, mxA, 1));
                mxA = fmaxf(mxA, __shfl_xor_sync(0xffffffffu, mxA, 2));
                mxB = fmaxf(mxB, __shfl_xor_sync(0xffffffffu, mxB, 1));
                mxB = fmaxf(mxB, __shfl_xor_sync(0xffffffffu, mxB, 2));
                float mnA = fmaxf(mS[stA], mxA);
                float mnB = fmaxf(mS[stB], mxB);
                float scA = exp2p(mS[stA] - mnA), scB = exp2p(mS[stB] - mnB);
                mS[stA] = mnA; mS[stB] = mnB;
                lS[stA] *= scA; lS[stB] *= scB;
                #pragma unroll
                for (int jb = 0; jb < NB_; jb++) { bsS[stA][jb] *= scA; bsS[stB][jb] *= scB; }
                float (*Oh)[4] = (h == 0) ? O0 : O1;
                #pragma unroll
                for (int nf = 0; nf < 8; nf++) {
                    Oh[nf][0] *= scA; Oh[nf][1] *= scA;
                    Oh[nf][2] *= scB; Oh[nf][3] *= scB;
                }
                #pragma unroll
                for (int nf = 0; nf < 4; nf++) {
                    #pragma unroll
                    for (int e = 0; e < 4; e++) {
                        float p = exp2p(s[nf][e] - ((e < 2) ? mnA : mnB));
                        s[nf][e] = p;
                        if (e < 2) { rsA += p; bsS[stA][jbs[nf][e]] += p; }
                        else       { rsB += p; bsS[stB][jbs[nf][e]] += p; }
                    }
                }
                lS[stA] += rsA; lS[stB] += rsB;
            }

            // store P half (tf32) -> Pw, STS.64
            #pragma unroll
            for (int nf = 0; nf < 4; nf++) {
                int c = (nf << 3) + (lr << 1);
                float2 pa = make_float2(f2tff(s[nf][0]), f2tff(s[nf][1]));
                float2 pb = make_float2(f2tff(s[nf][2]), f2tff(s[nf][3]));
                *(float2*)&sm.Pw[wid][(h << 4) + qd][c] = pa;
                *(float2*)&sm.Pw[wid][(h << 4) + qd + 8][c] = pb;
            }
        }
        __syncwarp();

        // O += P @ V, sharing V B-fragments across halves
        #pragma unroll
        for (int j = 0; j < 4; j++) {
            float a0[4], a1[4];
            a0[0] = sm.Pw[wid][qd][(j << 3) + lr];
            a0[1] = sm.Pw[wid][qd + 8][(j << 3) + lr];
            a0[2] = sm.Pw[wid][qd][(j << 3) + lr + 4];
            a0[3] = sm.Pw[wid][qd + 8][(j << 3) + lr + 4];
            a1[0] = sm.Pw[wid][16 + qd][(j << 3) + lr];
            a1[1] = sm.Pw[wid][24 + qd][(j << 3) + lr];
            a1[2] = sm.Pw[wid][16 + qd][(j << 3) + lr + 4];
            a1[3] = sm.Pw[wid][24 + qd][(j << 3) + lr + 4];
            #pragma unroll
            for (int nf = 0; nf < 8; nf++) {
                float b0 = Vc[(j << 3) + lr][(nf << 3) + qd];
                float b1 = Vc[(j << 3) + lr + 4][(nf << 3) + qd];
                mma8f(O0[nf], a0, b0, b1);
                mma8f(O1[nf], a1, b0, b1);
            }
        }
        __syncwarp();
    }

    // quad reductions
    #pragma unroll
    for (int st = 0; st < 4; st++) {
        #pragma unroll
        for (int o = 1; o <= 2; o <<= 1) {
            lS[st] += __shfl_xor_sync(0xffffffffu, lS[st], o);
            #pragma unroll
            for (int jb = 0; jb < NB_; jb++)
                bsS[st][jb] += __shfl_xor_sync(0xffffffffu, bsS[st][jb], o);
        }
    }

    const int bb = bh / H_, hh = bh % H_;
    #pragma unroll
    for (int h = 0; h < 2; h++) {
        float (*Oh)[4] = (h == 0) ? O0 : O1;
        #pragma unroll
        for (int rp = 0; rp < 2; rp++) {
            int st = (h << 1) + rp;
            float inv = 1.f / lS[st];
            int rg = q0 + rw + (h << 4) + qd + (rp << 3);
            #pragma unroll
            for (int nf = 0; nf < 8; nf++) {
                int d0 = (nf << 3) + (lr << 1);
                float o2a = 0.f, o2b = 0.f;
                #pragma unroll
                for (int jb = 0; jb < NB_; jb++) {
                    o2a += bsS[st][jb] * sm.rvS[jb][d0];
                    o2b += bsS[st][jb] * sm.rvS[jb][d0 + 1];
                }
                float2 w = make_float2(f2tff((Oh[nf][(rp << 1)] + o2a) * inv),
                                       f2tff((Oh[nf][(rp << 1) + 1] + o2b) * inv));
                *(float2*)&g_att[(((size_t)bb * S_ + rg) * H_ + hh) * D_ + d0] = w;
            }
        }
    }
}

// ---------------------------------------------------------------------------
extern "C" void kernel_launch(void* const* d_in, const int* in_sizes, int n_in,
                              void* d_out, int out_size) {
    const float* x    = (const float*)d_in[0];
    const float* Wq   = (const float*)d_in[1];
    const float* bq   = (const float*)d_in[2];
    const float* Wk   = (const float*)d_in[3];
    const float* bk   = (const float*)d_in[4];
    const float* Wv   = (const float*)d_in[5];
    const float* bv   = (const float*)d_in[6];
    const float* Wo   = (const float*)d_in[7];
    const float* bo   = (const float*)d_in[8];
    const float* relk = (const float*)d_in[9];
    const float* relv = (const float*)d_in[10];
    float* out = (float*)d_out;

    float *gq, *gk, *gv, *gatt, *gxr, *gwr;
    cudaGetSymbolAddress((void**)&gq,   g_q);
    cudaGetSymbolAddress((void**)&gk,   g_k);
    cudaGetSymbolAddress((void**)&gv,   g_v);
    cudaGetSymbolAddress((void**)&gatt, g_att);
    cudaGetSymbolAddress((void**)&gxr,  g_xr);
    cudaGetSymbolAddress((void**)&gwr,  g_wr);

    cudaFuncSetAttribute(gemm_tf32, cudaFuncAttributeMaxDynamicSharedMemorySize,
                         (int)sizeof(GSmem));
    cudaFuncSetAttribute(attn_tf32, cudaFuncAttributeMaxDynamicSharedMemorySize,
                         (int)sizeof(ASmem));

    round_pass<<<2048, 256>>>(x, Wq, Wk, Wv, Wo);

    const float* w0 = gwr;
    const float* w1 = gwr + 1024*1024;
    const float* w2 = gwr + 2*1024*1024;
    const float* w3 = gwr + 3*1024*1024;

    dim3 ggrid(DM_ / 128, (B_ * S_) / 128);
    gemm_tf32<<<ggrid, 256, sizeof(GSmem)>>>(gxr, w0, bq, gq, 1);
    gemm_tf32<<<ggrid, 256, sizeof(GSmem)>>>(gxr, w1, bk, gk, 1);
    gemm_tf32<<<ggrid, 256, sizeof(GSmem)>>>(gxr, w2, bv, gv, 1);
    attn_tf32<<<dim3(S_ / 128, B_ * H_), 128, sizeof(ASmem)>>>(relk, relv);
    gemm_tf32<<<ggrid, 256, sizeof(GSmem)>>>(gatt, w3, bo, out, 0);
}

// round 7
// speedup vs baseline: 3.6342x; 1.0333x over previous
#include <cuda_runtime.h>

#define B_   2
#define S_   2048
#define DM_  1024
#define H_   16
#define D_   64
#define NB_  5
#define SCALE_ 0.125f
#define LOG2E_ 1.4426950408889634f
#define ALPHA_ (SCALE_ * LOG2E_)

// Static device scratch
__device__ float g_q[B_*H_*S_*D_];
__device__ float g_k[B_*H_*S_*D_];
__device__ float g_v[B_*H_*S_*D_];
__device__ float g_att[B_*S_*DM_];
__device__ float g_xr[4096*1024];
__device__ float g_wr[4][1024*1024];

// ---------------------------------------------------------------------------
__device__ __forceinline__ unsigned f2tf(float x) {
    unsigned r;
    asm("cvt.rna.tf32.f32 %0, %1;" : "=r"(r) : "f"(x));
    return r;
}
__device__ __forceinline__ float f2tff(float x) { return __uint_as_float(f2tf(x)); }

__device__ __forceinline__ void mma8f(float* c, const float* a, float b0f, float b1f) {
    asm volatile(
        "mma.sync.aligned.m16n8k8.row.col.f32.tf32.tf32.f32 "
        "{%0,%1,%2,%3}, {%4,%5,%6,%7}, {%8,%9}, {%0,%1,%2,%3};"
        : "+f"(c[0]), "+f"(c[1]), "+f"(c[2]), "+f"(c[3])
        : "r"(__float_as_uint(a[0])), "r"(__float_as_uint(a[1])),
          "r"(__float_as_uint(a[2])), "r"(__float_as_uint(a[3])),
          "r"(__float_as_uint(b0f)), "r"(__float_as_uint(b1f)));
}

#define CP16(dst_smem, src) \
    asm volatile("cp.async.cg.shared.global [%0], [%1], 16;\n" :: \
        "r"((unsigned)__cvta_generic_to_shared(dst_smem)), "l"(src) : "memory")
#define CP_COMMIT() asm volatile("cp.async.commit_group;\n" ::: "memory")
#define CP_WAIT0()  asm volatile("cp.async.wait_group 0;\n" ::: "memory")
#define CP_WAIT1()  asm volatile("cp.async.wait_group 1;\n" ::: "memory")

// exp2 on FMA pipe. Valid for y <= 0; clamps at -28.
__device__ __forceinline__ float exp2p(float y) {
    y = fmaxf(y, -28.f);
    float t = y + 12582912.0f;
    float fl = t - 12582912.0f;
    float f = y - fl;
    float p = fmaf(1.5403530e-4f, f, 1.3333558e-3f);
    p = fmaf(p, f, 9.6181291e-3f);
    p = fmaf(p, f, 5.5504109e-2f);
    p = fmaf(p, f, 2.4022651e-1f);
    p = fmaf(p, f, 6.9314718e-1f);
    p = fmaf(p, f, 1.0f);
    int e = ((__float_as_int(t) & 0x7FFFFF) - 0x400000 + 127) << 23;
    return p * __int_as_float(e);
}

// ---------------------------------------------------------------------------
// Pre-pass: tf32-round x and the 4 weight matrices.
// ---------------------------------------------------------------------------
__global__ void round_pass(const float* __restrict__ x,  const float* __restrict__ wq,
                           const float* __restrict__ wk, const float* __restrict__ wv,
                           const float* __restrict__ wo)
{
    const int total = 1048576 + 4 * 262144;
    for (int i = blockIdx.x * blockDim.x + threadIdx.x; i < total;
         i += gridDim.x * blockDim.x) {
        const float4* src; float4* dst; int off;
        if (i < 1048576) { src = (const float4*)x; dst = (float4*)g_xr; off = i; }
        else {
            int j = i - 1048576; int seg = j >> 18; off = j & 262143;
            const float* s4 = (seg == 0) ? wq : (seg == 1) ? wk : (seg == 2) ? wv : wo;
            src = (const float4*)s4; dst = (float4*)g_wr[seg];
        }
        float4 v = src[off];
        v.x = f2tff(v.x); v.y = f2tff(v.y); v.z = f2tff(v.z); v.w = f2tff(v.w);
        dst[off] = v;
    }
}

// ---------------------------------------------------------------------------
// TF32 GEMM core: 128x128 tile, 256 thr, k-step 32, 3-stage cp.async pipeline.
// ---------------------------------------------------------------------------
struct GSmem {
    float Xs[3][128][36];
    float Ws[3][32][132];
};

__device__ __forceinline__ void gemm_body(
    GSmem& sm, const float* __restrict__ X, const float* __restrict__ W,
    const float* __restrict__ bias, float* __restrict__ out, int permute,
    int m0, int n0)
{
    const int tid  = threadIdx.x;
    const int lane = tid & 31, wid = tid >> 5;
    const int qd = lane >> 2, lr = lane & 3;
    const int wm = wid >> 2, wn = wid & 3;

    const int xr = tid >> 3, xc = (tid & 7) << 2;
    const int wr = tid >> 5, wc = (tid & 31) << 2;

    auto load_tile = [&](int buf, int k0) {
        #pragma unroll
        for (int it = 0; it < 4; it++)
            CP16(&sm.Xs[buf][xr + (it << 5)][xc],
                 &X[(size_t)(m0 + xr + (it << 5)) * DM_ + k0 + xc]);
        #pragma unroll
        for (int it = 0; it < 4; it++)
            CP16(&sm.Ws[buf][wr + (it << 3)][wc],
                 &W[(size_t)(k0 + wr + (it << 3)) * DM_ + n0 + wc]);
    };

    load_tile(0, 0);  CP_COMMIT();
    load_tile(1, 32); CP_COMMIT();

    float acc[4][4][4] = {};
    int buf = 0;

    for (int kt = 0; kt < DM_ / 32; kt++) {
        CP_WAIT1();
        __syncthreads();
        if (kt + 2 < DM_ / 32) {
            int nb = buf + 2; if (nb >= 3) nb -= 3;
            load_tile(nb, (kt + 2) << 5);
            CP_COMMIT();
        }

        #pragma unroll
        for (int ks = 0; ks < 4; ks++) {
            int kk = ks << 3;
            float a[4][4], b[4][2];
            #pragma unroll
            for (int mf = 0; mf < 4; mf++) {
                int r = (wm << 6) + (mf << 4) + qd;
                a[mf][0] = sm.Xs[buf][r][kk + lr];
                a[mf][1] = sm.Xs[buf][r + 8][kk + lr];
                a[mf][2] = sm.Xs[buf][r][kk + lr + 4];
                a[mf][3] = sm.Xs[buf][r + 8][kk + lr + 4];
            }
            #pragma unroll
            for (int nf = 0; nf < 4; nf++) {
                int n = (wn << 5) + (nf << 3) + qd;
                b[nf][0] = sm.Ws[buf][kk + lr][n];
                b[nf][1] = sm.Ws[buf][kk + lr + 4][n];
            }
            #pragma unroll
            for (int mf = 0; mf < 4; mf++)
                #pragma unroll
                for (int nf = 0; nf < 4; nf++)
                    mma8f(acc[mf][nf], a[mf], b[nf][0], b[nf][1]);
        }
        __syncthreads();
        if (++buf >= 3) buf -= 3;
    }

    #pragma unroll
    for (int mf = 0; mf < 4; mf++) {
        #pragma unroll
        for (int nf = 0; nf < 4; nf++) {
            #pragma unroll
            for (int rp = 0; rp < 2; rp++) {
                int m = m0 + (wm << 6) + (mf << 4) + qd + (rp << 3);
                int n = n0 + (wn << 5) + (nf << 3) + (lr << 1);
                float v0 = acc[mf][nf][(rp << 1)]     + bias[n];
                float v1 = acc[mf][nf][(rp << 1) + 1] + bias[n + 1];
                if (permute) {
                    int bb = m >> 11, s = m & (S_ - 1);
                    int h = n >> 6, d = n & 63;
                    float2 w = make_float2(f2tff(v0), f2tff(v1));
                    *(float2*)&out[(((bb * H_ + h) * S_) + s) * D_ + d] = w;
                } else {
                    *(float2*)&out[(size_t)m * DM_ + n] = make_float2(v0, v1);
                }
            }
        }
    }
}

__global__ __launch_bounds__(256) void gemm_qkv(
    const float* __restrict__ X,
    const float* __restrict__ W0, const float* __restrict__ W1, const float* __restrict__ W2,
    const float* __restrict__ b0, const float* __restrict__ b1, const float* __restrict__ b2,
    float* __restrict__ o0, float* __restrict__ o1, float* __restrict__ o2)
{
    extern __shared__ char graw[];
    GSmem& sm = *reinterpret_cast<GSmem*>(graw);
    const int z = blockIdx.z;
    const float* W = (z == 0) ? W0 : (z == 1) ? W1 : W2;
    const float* bs = (z == 0) ? b0 : (z == 1) ? b1 : b2;
    float* out = (z == 0) ? o0 : (z == 1) ? o1 : o2;
    gemm_body(sm, X, W, bs, out, 1, blockIdx.y << 7, blockIdx.x << 7);
}

__global__ __launch_bounds__(256) void gemm_out(
    const float* __restrict__ X, const float* __restrict__ W,
    const float* __restrict__ bias, float* __restrict__ out)
{
    extern __shared__ char graw[];
    GSmem& sm = *reinterpret_cast<GSmem*>(graw);
    gemm_body(sm, X, W, bias, out, 0, blockIdx.y << 7, blockIdx.x << 7);
}

// ---------------------------------------------------------------------------
// Flash attention: q-tile 128, m32/warp (4 warps), k-tile 32, cp.async DB.
// P transposed C->A layout via register shuffles (no smem round trip).
// ---------------------------------------------------------------------------
struct ASmem {
    float Ks[2][32][68];
    float Vs[2][32][72];
    float qrelS[128][8];
    float rkS[NB_][64];
    float rvS[NB_][64];
};

__global__ __launch_bounds__(128, 2) void attn_tf32(
    const float* __restrict__ rel_k, const float* __restrict__ rel_v)
{
    extern __shared__ char sraw[];
    ASmem& sm = *reinterpret_cast<ASmem*>(sraw);
    const int tid = threadIdx.x;
    const int lane = tid & 31, wid = tid >> 5;
    const int qd = lane >> 2, lr = lane & 3;
    const bool odd = lr & 1;
    const int src0 = (lane & 28) | (lr >> 1);
    const int src1 = src0 + 2;
    const int q0 = blockIdx.x << 7;
    const int bh = blockIdx.y;
    const float* qptr = g_q + (size_t)bh * S_ * D_;
    const float* kptr = g_k + (size_t)bh * S_ * D_;
    const float* vptr = g_v + (size_t)bh * S_ * D_;

    auto load_kv = [&](int buf, int k0) {
        #pragma unroll
        for (int it = 0; it < 4; it++) {
            int idx = tid + (it << 7);
            int r = idx >> 4, c4 = (idx & 15) << 2;
            CP16(&sm.Ks[buf][r][c4], &kptr[(size_t)(k0 + r) * D_ + c4]);
            CP16(&sm.Vs[buf][r][c4], &vptr[(size_t)(k0 + r) * D_ + c4]);
        }
    };

    load_kv(0, 0);
    CP_COMMIT();

    for (int t = tid; t < NB_ * 64; t += 128) {
        sm.rkS[t >> 6][t & 63] = rel_k[t];
        sm.rvS[t >> 6][t & 63] = rel_v[t];
    }

    // Q fragments straight from gmem (pre-rounded tf32)
    const int rw = wid << 5;
    float qf[2][8][4];
    #pragma unroll
    for (int h = 0; h < 2; h++) {
        const float* qr0 = &qptr[(size_t)(q0 + rw + (h << 4) + qd) * D_];
        #pragma unroll
        for (int kf = 0; kf < 8; kf++) {
            qf[h][kf][0] = __ldg(&qr0[(kf << 3) + lr]);
            qf[h][kf][1] = __ldg(&qr0[(size_t)8 * D_ + (kf << 3) + lr]);
            qf[h][kf][2] = __ldg(&qr0[(kf << 3) + lr + 4]);
            qf[h][kf][3] = __ldg(&qr0[(size_t)8 * D_ + (kf << 3) + lr + 4]);
        }
    }
    __syncthreads();

    // qrel[r][jb] from register Q frags
    #pragma unroll
    for (int st = 0; st < 4; st++) {
        int h = st >> 1, rp = st & 1;
        int rloc = rw + (h << 4) + qd + (rp << 3);
        #pragma unroll
        for (int jb = 0; jb < NB_; jb++) {
            float acc = 0.f;
            #pragma unroll
            for (int kf = 0; kf < 8; kf++) {
                acc += qf[h][kf][rp]     * sm.rkS[jb][(kf << 3) + lr];
                acc += qf[h][kf][rp + 2] * sm.rkS[jb][(kf << 3) + lr + 4];
            }
            acc += __shfl_xor_sync(0xffffffffu, acc, 1);
            acc += __shfl_xor_sync(0xffffffffu, acc, 2);
            if (lr == 0) sm.qrelS[rloc][jb] = acc;
        }
    }
    __syncthreads();

    float O0[8][4] = {}, O1[8][4] = {};
    float mS[4], lS[4], bsS[4][NB_] = {};
    #pragma unroll
    for (int st = 0; st < 4; st++) { mS[st] = -1e30f; lS[st] = 0.f; }
    const int rmin = q0 + rw;

    for (int kt = 0; kt < S_ / 32; kt++) {
        const int k0 = kt << 5;
        const int cur = kt & 1;
        CP_WAIT0();
        __syncthreads();
        if (kt + 1 < S_ / 32) { load_kv(cur ^ 1, k0 + 32); CP_COMMIT(); }

        const float (*Kc)[68] = sm.Ks[cur];
        const float (*Vc)[72] = sm.Vs[cur];

        // S = Q @ K^T for both halves, shared B fragments
        float s0[4][4] = {}, s1[4][4] = {};
        #pragma unroll
        for (int kf = 0; kf < 8; kf++) {
            #pragma unroll
            for (int nf = 0; nf < 4; nf++) {
                float b0 = Kc[(nf << 3) + qd][(kf << 3) + lr];
                float b1 = Kc[(nf << 3) + qd][(kf << 3) + lr + 4];
                mma8f(s0[nf], qf[0][kf], b0, b1);
                mma8f(s1[nf], qf[1][kf], b0, b1);
            }
        }

        bool mixed = (k0 > rmin - 34) && (k0 < rmin + 34);

        #pragma unroll
        for (int h = 0; h < 2; h++) {
            float (*s)[4] = (h == 0) ? s0 : s1;
            int stA = h << 1, stB = stA + 1;
            int rlA = rw + (h << 4) + qd;
            int rgA = q0 + rlA, rgB = rgA + 8;
            float rsA = 0.f, rsB = 0.f;

            if (!mixed) {
                const int bkt = (k0 >= rmin + 34) ? 4 : 0;
                float qbA = sm.qrelS[rlA][bkt] * ALPHA_;
                float qbB = sm.qrelS[rlA + 8][bkt] * ALPHA_;
                float mxA = -1e30f, mxB = -1e30f;
                #pragma unroll
                for (int nf = 0; nf < 4; nf++) {
                    mxA = fmaxf(mxA, fmaxf(s[nf][0], s[nf][1]));
                    mxB = fmaxf(mxB, fmaxf(s[nf][2], s[nf][3]));
                }
                mxA = fmaxf(mxA, __shfl_xor_sync(0xffffffffu, mxA, 1));
                mxA = fmaxf(mxA, __shfl_xor_sync(0xffffffffu, mxA, 2));
                mxB = fmaxf(mxB, __shfl_xor_sync(0xffffffffu, mxB, 1));
                mxB = fmaxf(mxB, __shfl_xor_sync(0xffffffffu, mxB, 2));
                float mnA = fmaxf(mS[stA], fmaf(mxA, ALPHA_, qbA));
                float mnB = fmaxf(mS[stB], fmaf(mxB, ALPHA_, qbB));
                if (__any_sync(0xffffffffu, (mnA > mS[stA]) | (mnB > mS[stB]))) {
                    float scA = exp2p(mS[stA] - mnA), scB = exp2p(mS[stB] - mnB);
                    lS[stA] *= scA; lS[stB] *= scB;
                    #pragma unroll
                    for (int jb = 0; jb < NB_; jb++) { bsS[stA][jb] *= scA; bsS[stB][jb] *= scB; }
                    float (*Oh)[4] = (h == 0) ? O0 : O1;
                    #pragma unroll
                    for (int nf = 0; nf < 8; nf++) {
                        Oh[nf][0] *= scA; Oh[nf][1] *= scA;
                        Oh[nf][2] *= scB; Oh[nf][3] *= scB;
                    }
                }
                mS[stA] = mnA; mS[stB] = mnB;
                float cA = qbA - mnA, cB = qbB - mnB;
                #pragma unroll
                for (int nf = 0; nf < 4; nf++) {
                    float p0 = exp2p(fmaf(s[nf][0], ALPHA_, cA));
                    float p1 = exp2p(fmaf(s[nf][1], ALPHA_, cA));
                    float p2 = exp2p(fmaf(s[nf][2], ALPHA_, cB));
                    float p3 = exp2p(fmaf(s[nf][3], ALPHA_, cB));
                    s[nf][0] = p0; s[nf][1] = p1; s[nf][2] = p2; s[nf][3] = p3;
                    rsA += p0 + p1; rsB += p2 + p3;
                }
                lS[stA] += rsA; lS[stB] += rsB;
                bsS[stA][bkt] += rsA; bsS[stB][bkt] += rsB;
            } else {
                float mxA = -1e30f, mxB = -1e30f;
                int jbs[4][4];
                #pragma unroll
                for (int nf = 0; nf < 4; nf++) {
                    #pragma unroll
                    for (int e = 0; e < 4; e++) {
                        int kp = k0 + (nf << 3) + (lr << 1) + (e & 1);
                        int rg = (e < 2) ? rgA : rgB;
                        int rl = (e < 2) ? rlA : rlA + 8;
                        int jb = min(max(kp - rg, -2), 2) + 2;
                        jbs[nf][e] = jb;
                        float y = (s[nf][e] + sm.qrelS[rl][jb]) * ALPHA_;
                        s[nf][e] = y;
                        if (e < 2) mxA = fmaxf(mxA, y); else mxB = fmaxf(mxB, y);
                    }
                }
                mxA = fmaxf(mxA, __shfl_xor_sync(0xffffffffu, mxA, 1));
                mxA = fmaxf(mxA, __shfl_xor_sync(0xffffffffu, mxA, 2));
                mxB = fmaxf(mxB, __shfl_xor_sync(0xffffffffu, mxB, 1));
                mxB = fmaxf(mxB, __shfl_xor_sync(0xffffffffu, mxB, 2));
                float mnA = fmaxf(mS[stA], mxA);
                float mnB = fmaxf(mS[stB], mxB);
                float scA = exp2p(mS[stA] - mnA), scB = exp2p(mS[stB] - mnB);
                mS[stA] = mnA; mS[stB] = mnB;
                lS[stA] *= scA; lS[stB] *= scB;
                #pragma unroll
                for (int jb = 0; jb < NB_; jb++) { bsS[stA][jb] *= scA; bsS[stB][jb] *= scB; }
                float (*Oh)[4] = (h == 0) ? O0 : O1;
                #pragma unroll
                for (int nf = 0; nf < 8; nf++) {
                    Oh[nf][0] *= scA; Oh[nf][1] *= scA;
                    Oh[nf][2] *= scB; Oh[nf][3] *= scB;
                }
                #pragma unroll
                for (int nf = 0; nf < 4; nf++) {
                    #pragma unroll
                    for (int e = 0; e < 4; e++) {
                        float p = exp2p(s[nf][e] - ((e < 2) ? mnA : mnB));
                        s[nf][e] = p;
                        if (e < 2) { rsA += p; bsS[stA][jbs[nf][e]] += p; }
                        else       { rsB += p; bsS[stB][jbs[nf][e]] += p; }
                    }
                }
                lS[stA] += rsA; lS[stB] += rsB;
            }
        }

        // O += P @ V. P C-layout -> A-layout via quad shuffles, V B-frags shared.
        #pragma unroll
        for (int j = 0; j < 4; j++) {
            float a0[4], a1[4];
            {
                float c0 = f2tff(s0[j][0]), c1 = f2tff(s0[j][1]);
                float c2 = f2tff(s0[j][2]), c3 = f2tff(s0[j][3]);
                float t00 = __shfl_sync(0xffffffffu, c0, src0);
                float t10 = __shfl_sync(0xffffffffu, c1, src0);
                float t20 = __shfl_sync(0xffffffffu, c2, src0);
                float t30 = __shfl_sync(0xffffffffu, c3, src0);
                float t01 = __shfl_sync(0xffffffffu, c0, src1);
                float t11 = __shfl_sync(0xffffffffu, c1, src1);
                float t21 = __shfl_sync(0xffffffffu, c2, src1);
                float t31 = __shfl_sync(0xffffffffu, c3, src1);
                a0[0] = odd ? t10 : t00; a0[1] = odd ? t30 : t20;
                a0[2] = odd ? t11 : t01; a0[3] = odd ? t31 : t21;
            }
            {
                float c0 = f2tff(s1[j][0]), c1 = f2tff(s1[j][1]);
                float c2 = f2tff(s1[j][2]), c3 = f2tff(s1[j][3]);
                float t00 = __shfl_sync(0xffffffffu, c0, src0);
                float t10 = __shfl_sync(0xffffffffu, c1, src0);
                float t20 = __shfl_sync(0xffffffffu, c2, src0);
                float t30 = __shfl_sync(0xffffffffu, c3, src0);
                float t01 = __shfl_sync(0xffffffffu, c0, src1);
                float t11 = __shfl_sync(0xffffffffu, c1, src1);
                float t21 = __shfl_sync(0xffffffffu, c2, src1);
                float t31 = __shfl_sync(0xffffffffu, c3, src1);
                a1[0] = odd ? t10 : t00; a1[1] = odd ? t30 : t20;
                a1[2] = odd ? t11 : t01; a1[3] = odd ? t31 : t21;
            }
            #pragma unroll
            for (int nf = 0; nf < 8; nf++) {
                float b0 = Vc[(j << 3) + lr][(nf << 3) + qd];
                float b1 = Vc[(j << 3) + lr + 4][(nf << 3) + qd];
                mma8f(O0[nf], a0, b0, b1);
                mma8f(O1[nf], a1, b0, b1);
            }
        }
    }

    // quad reductions
    #pragma unroll
    for (int st = 0; st < 4; st++) {
        #pragma unroll
        for (int o = 1; o <= 2; o <<= 1) {
            lS[st] += __shfl_xor_sync(0xffffffffu, lS[st], o);
            #pragma unroll
            for (int jb = 0; jb < NB_; jb++)
                bsS[st][jb] += __shfl_xor_sync(0xffffffffu, bsS[st][jb], o);
        }
    }

    const int bb = bh / H_, hh = bh % H_;
    #pragma unroll
    for (int h = 0; h < 2; h++) {
        float (*Oh)[4] = (h == 0) ? O0 : O1;
        #pragma unroll
        for (int rp = 0; rp < 2; rp++) {
            int st = (h << 1) + rp;
            float inv = 1.f / lS[st];
            int rg = q0 + rw + (h << 4) + qd + (rp << 3);
            #pragma unroll
            for (int nf = 0; nf < 8; nf++) {
                int d0 = (nf << 3) + (lr << 1);
                float o2a = 0.f, o2b = 0.f;
                #pragma unroll
                for (int jb = 0; jb < NB_; jb++) {
                    o2a += bsS[st][jb] * sm.rvS[jb][d0];
                    o2b += bsS[st][jb] * sm.rvS[jb][d0 + 1];
                }
                float2 w = make_float2(f2tff((Oh[nf][(rp << 1)] + o2a) * inv),
                                       f2tff((Oh[nf][(rp << 1) + 1] + o2b) * inv));
                *(float2*)&g_att[(((size_t)bb * S_ + rg) * H_ + hh) * D_ + d0] = w;
            }
        }
    }
}

// ---------------------------------------------------------------------------
extern "C" void kernel_launch(void* const* d_in, const int* in_sizes, int n_in,
                              void* d_out, int out_size) {
    const float* x    = (const float*)d_in[0];
    const float* Wq   = (const float*)d_in[1];
    const float* bq   = (const float*)d_in[2];
    const float* Wk   = (const float*)d_in[3];
    const float* bk   = (const float*)d_in[4];
    const float* Wv   = (const float*)d_in[5];
    const float* bv   = (const float*)d_in[6];
    const float* Wo   = (const float*)d_in[7];
    const float* bo   = (const float*)d_in[8];
    const float* relk = (const float*)d_in[9];
    const float* relv = (const float*)d_in[10];
    float* out = (float*)d_out;

    float *gq, *gk, *gv, *gatt, *gxr, *gwr;
    cudaGetSymbolAddress((void**)&gq,   g_q);
    cudaGetSymbolAddress((void**)&gk,   g_k);
    cudaGetSymbolAddress((void**)&gv,   g_v);
    cudaGetSymbolAddress((void**)&gatt, g_att);
    cudaGetSymbolAddress((void**)&gxr,  g_xr);
    cudaGetSymbolAddress((void**)&gwr,  g_wr);

    cudaFuncSetAttribute(gemm_qkv, cudaFuncAttributeMaxDynamicSharedMemorySize,
                         (int)sizeof(GSmem));
    cudaFuncSetAttribute(gemm_out, cudaFuncAttributeMaxDynamicSharedMemorySize,
                         (int)sizeof(GSmem));
    cudaFuncSetAttribute(attn_tf32, cudaFuncAttributeMaxDynamicSharedMemorySize,
                         (int)sizeof(ASmem));

    round_pass<<<2048, 256>>>(x, Wq, Wk, Wv, Wo);

    const float* w0 = gwr;
    const float* w1 = gwr + 1024*1024;
    const float* w2 = gwr + 2*1024*1024;
    const float* w3 = gwr + 3*1024*1024;

    dim3 gq3(DM_ / 128, (B_ * S_) / 128, 3);
    gemm_qkv<<<gq3, 256, sizeof(GSmem)>>>(gxr, w0, w1, w2, bq, bk, bv, gq, gk, gv);
    attn_tf32<<<dim3(S_ / 128, B_ * H_), 128, sizeof(ASmem)>>>(relk, relv);
    gemm_out<<<dim3(DM_ / 128, (B_ * S_) / 128), 256, sizeof(GSmem)>>>(gatt, w3, bo, out);
}